// round 1
// baseline (speedup 1.0000x reference)
#include <cuda_runtime.h>
#include <math.h>

// ---------------------------------------------------------------------------
// RelNet forward, fp32 baseline.
//   convs:   4x (conv3x3 s2 p1 + bias + relu), batch-stat BN folded into the
//            NEXT consumer as per-channel scale/shift (no normalize pass).
//   g1:      decomposed into P (i-role), Q (j-role), R (question+bias).
//   g2..g4:  fused per-tile GEMM chain, activations live in smem, weights
//            pre-transposed so all global loads are float4-coalesced.
//   head:    f1->fc2->fc3->log_softmax, one block per batch row.
// ---------------------------------------------------------------------------

#define NB     512
#define NFS    24
#define HID    256
#define NOBJ   25
#define NPAIR  625      // 25*25
#define TM     48       // pairs per g-MLP tile (48*256*4B = 48KB smem exactly)
#define NTILE  14       // ceil(625/48)
#define NTHR_G 384      // (TM/4) * 32

// ------------------------- device scratch (static, no allocs) ---------------
__device__ float d_y1[NB*NFS*40*40];
__device__ float d_y2[NB*NFS*20*20];
__device__ float d_y3[NB*NFS*10*10];
__device__ float d_y4[NB*NFS*25];
__device__ float d_stats[4*48];       // [layer][ sum(24) | sumsq(24) ]
__device__ float d_bnp[4*48];         // [layer][ scale(24) | shift(24) ]
__device__ float d_P[NB*NOBJ*HID];
__device__ float d_Q[NB*NOBJ*HID];
__device__ float d_R[NB*HID];
__device__ float d_xg[NB*HID];
__device__ float d_Wt[5*HID*HID];     // g2,g3,g4,f1,fc2 transposed: Wt[k][n]

// ------------------------------ zero init -----------------------------------
__global__ void zero_kernel() {
    int i = blockIdx.x * 256 + threadIdx.x;
    if (i < NB*HID) d_xg[i] = 0.f;
    if (i < 4*48)   d_stats[i] = 0.f;
}

// ------------------------------ transpose -----------------------------------
__global__ void transpose5_kernel(const float* __restrict__ g2w,
                                  const float* __restrict__ g3w,
                                  const float* __restrict__ g4w,
                                  const float* __restrict__ f1w,
                                  const float* __restrict__ fc2w) {
    int idx = blockIdx.x * 256 + threadIdx.x;
    if (idx >= 5*HID*HID) return;
    int t = idx >> 16;
    int r = idx & 65535;
    int k = r >> 8;
    int n = r & 255;
    const float* src = (t == 0) ? g2w : (t == 1) ? g3w : (t == 2) ? g4w
                      : (t == 3) ? f1w : fc2w;
    d_Wt[idx] = src[n*HID + k];
}

// --------------------------- conv + relu + stats -----------------------------
// One output element per thread; block is a single output channel so the
// BN-stat reduction is per-channel. BN of the *input* is applied inline via
// d_bnp[bn_idx] (identity for conv1).
__global__ void conv_bn_kernel(const float* __restrict__ in, float* __restrict__ out,
                               const float* __restrict__ w, const float* __restrict__ cb,
                               int stats_idx, int bn_idx,
                               int C_in, int H_in, int H_out) {
    __shared__ float ws[NFS*9];
    __shared__ float sc[NFS], sh[NFS];
    __shared__ float red1[8], red2[8];

    const int co  = blockIdx.y;
    const int tid = threadIdx.x;
    const int nw  = C_in * 9;
    for (int i = tid; i < nw; i += 256) ws[i] = w[co*nw + i];
    if (bn_idx >= 0 && tid < C_in) {
        sc[tid] = d_bnp[bn_idx*48 + tid];
        sh[tid] = d_bnp[bn_idx*48 + 24 + tid];
    }
    __syncthreads();

    const int HW    = H_out * H_out;
    const int total = NB * HW;
    const int idx   = blockIdx.x * 256 + tid;

    float y = 0.f;
    if (idx < total) {
        const int n   = idx / HW;
        const int rem = idx - n*HW;
        const int oy  = rem / H_out;
        const int ox  = rem - oy*H_out;
        float acc = cb[co];
        const float* inb = in + (size_t)n * C_in * H_in * H_in;
        for (int ci = 0; ci < C_in; ci++) {
            const float* ic = inb + ci * H_in * H_in;
            const float s = (bn_idx >= 0) ? sc[ci] : 1.f;
            const float t = (bn_idx >= 0) ? sh[ci] : 0.f;
            const float* wr = ws + ci*9;
            #pragma unroll
            for (int ky = 0; ky < 3; ky++) {
                const int iy = 2*oy - 1 + ky;
                if (iy < 0 || iy >= H_in) continue;
                #pragma unroll
                for (int kx = 0; kx < 3; kx++) {
                    const int ix = 2*ox - 1 + kx;
                    if (ix < 0 || ix >= H_in) continue;
                    acc = fmaf(wr[ky*3+kx], fmaf(ic[iy*H_in + ix], s, t), acc);
                }
            }
        }
        y = fmaxf(acc, 0.f);
        out[((size_t)n*NFS + co)*HW + rem] = y;
    }

    // per-block partial sums for batch-stat BN
    float v1 = y, v2 = y*y;
    #pragma unroll
    for (int off = 16; off; off >>= 1) {
        v1 += __shfl_down_sync(0xffffffffu, v1, off);
        v2 += __shfl_down_sync(0xffffffffu, v2, off);
    }
    const int wid = tid >> 5;
    if ((tid & 31) == 0) { red1[wid] = v1; red2[wid] = v2; }
    __syncthreads();
    if (tid == 0) {
        float a = 0.f, b = 0.f;
        #pragma unroll
        for (int i = 0; i < 8; i++) { a += red1[i]; b += red2[i]; }
        atomicAdd(&d_stats[stats_idx*48 + co], a);
        atomicAdd(&d_stats[stats_idx*48 + 24 + co], b);
    }
}

__global__ void bn_finalize_kernel(int layer, float inv_count,
                                   const float* __restrict__ gamma,
                                   const float* __restrict__ beta) {
    int c = threadIdx.x;
    if (c >= NFS) return;
    float mean = d_stats[layer*48 + c] * inv_count;
    float var  = d_stats[layer*48 + 24 + c] * inv_count - mean*mean;
    float s    = gamma[c] * rsqrtf(var + 1e-5f);
    d_bnp[layer*48 + c]      = s;
    d_bnp[layer*48 + 24 + c] = beta[c] - mean * s;
}

// -------------------- g1 decomposition: P, Q, R ------------------------------
// block = (b, o); thread n in [0,256). objfeat = BN4(conv4 out) ++ coords.
__global__ void proj_kernel(const float* __restrict__ qst,
                            const float* __restrict__ g1w,
                            const float* __restrict__ g1b) {
    __shared__ float feat[26];
    const int blk = blockIdx.x;
    const int b = blk / NOBJ;
    const int o = blk - b*NOBJ;
    const int tid = threadIdx.x;

    if (tid < 24)       feat[tid] = d_y4[((size_t)b*NFS + tid)*25 + o] * d_bnp[3*48 + tid]
                                    + d_bnp[3*48 + 24 + tid];
    else if (tid == 24) feat[24] = ((float)(o / 5) - 2.f) * 0.5f;
    else if (tid == 25) feat[25] = ((float)(o % 5) - 2.f) * 0.5f;
    __syncthreads();

    const int n = tid;
    const float* wr = g1w + n*63;
    float p = 0.f, q = 0.f;
    #pragma unroll
    for (int c = 0; c < 26; c++) {
        const float f = feat[c];
        p = fmaf(wr[c],      f, p);
        q = fmaf(wr[26 + c], f, q);
    }
    d_P[((size_t)b*NOBJ + o)*HID + n] = p;
    d_Q[((size_t)b*NOBJ + o)*HID + n] = q;

    if (o == 0) {
        float r = g1b[n];
        #pragma unroll
        for (int c = 0; c < 11; c++) r = fmaf(wr[52 + c], qst[c*NB + b], r);
        d_R[(size_t)b*HID + n] = r;
    }
}

// -------------------------- fused g2/g3/g4 MLP -------------------------------
// grid (NTILE, NB). Each CTA owns TM=48 pairs of one batch row; h lives in
// 48KB smem through all three layers; outputs are staged in registers so the
// single buffer can be overwritten. Thread (tm,tn) computes a 4x8 microtile.
__global__ void __launch_bounds__(NTHR_G)
gmlp_kernel(const float* __restrict__ g2b,
            const float* __restrict__ g3b,
            const float* __restrict__ g4b) {
    __shared__ float h[TM][HID];                 // exactly 48KB

    const int b   = blockIdx.y;
    const int t   = blockIdx.x;
    const int tid = threadIdx.x;

    // ---- stage 1: h1 = relu(P[b,i] + Q[b,j] + R[b]) for this tile ----
    const float* Pb = d_P + (size_t)b*NOBJ*HID;
    const float* Qb = d_Q + (size_t)b*NOBJ*HID;
    const float* Rb = d_R + (size_t)b*HID;
    for (int idx = tid; idx < TM*HID; idx += NTHR_G) {
        const int r = idx >> 8;
        const int n = idx & 255;
        int p = t*TM + r;
        if (p >= NPAIR) p = 0;                    // pad rows masked later
        const int jj = p / NOBJ;
        const int ii = p - jj*NOBJ;
        const float v = Pb[ii*HID + n] + Qb[jj*HID + n] + Rb[n];
        h[r][n] = fmaxf(v, 0.f);
    }

    const int tn = tid & 31;
    const int tm = tid >> 5;                      // 0..11
    const int m0 = tm * 4;
    const int n0 = tn * 8;

    float acc[4][8];
    for (int L = 0; L < 3; L++) {
        __syncthreads();                          // h ready for this layer

        #pragma unroll
        for (int mm = 0; mm < 4; mm++)
            #pragma unroll
            for (int nn = 0; nn < 8; nn++) acc[mm][nn] = 0.f;

        const float* W = d_Wt + (size_t)L*HID*HID;  // Wt[k][n]

        #pragma unroll 2
        for (int k = 0; k < HID; k += 4) {
            float ha[4][4];
            #pragma unroll
            for (int mm = 0; mm < 4; mm++) {
                const float4 v = *(const float4*)&h[m0 + mm][k];
                ha[mm][0] = v.x; ha[mm][1] = v.y; ha[mm][2] = v.z; ha[mm][3] = v.w;
            }
            #pragma unroll
            for (int kk = 0; kk < 4; kk++) {
                const float4 w0 = *(const float4*)(W + (size_t)(k + kk)*HID + n0);
                const float4 w1 = *(const float4*)(W + (size_t)(k + kk)*HID + n0 + 4);
                const float wv[8] = {w0.x, w0.y, w0.z, w0.w, w1.x, w1.y, w1.z, w1.w};
                #pragma unroll
                for (int mm = 0; mm < 4; mm++) {
                    const float a = ha[mm][kk];
                    #pragma unroll
                    for (int nn = 0; nn < 8; nn++)
                        acc[mm][nn] = fmaf(a, wv[nn], acc[mm][nn]);
                }
            }
        }

        const float* bias = (L == 0) ? g2b : (L == 1) ? g3b : g4b;
        float bb[8];
        #pragma unroll
        for (int nn = 0; nn < 8; nn++) bb[nn] = bias[n0 + nn];

        __syncthreads();                          // all reads of h complete

        if (L < 2) {
            #pragma unroll
            for (int mm = 0; mm < 4; mm++)
                #pragma unroll
                for (int nn = 0; nn < 8; nn++)
                    h[m0 + mm][n0 + nn] = fmaxf(acc[mm][nn] + bb[nn], 0.f);
        } else {
            // masked row-sum over valid pairs, then CTA reduce + atomic
            const int pbase = t*TM + m0;
            float s[8];
            #pragma unroll
            for (int nn = 0; nn < 8; nn++) s[nn] = 0.f;
            #pragma unroll
            for (int mm = 0; mm < 4; mm++) {
                if (pbase + mm < NPAIR) {
                    #pragma unroll
                    for (int nn = 0; nn < 8; nn++)
                        s[nn] += fmaxf(acc[mm][nn] + bb[nn], 0.f);
                }
            }
            #pragma unroll
            for (int nn = 0; nn < 8; nn++) h[tm][n0 + nn] = s[nn];
            __syncthreads();
            if (tid < HID) {
                float tot = 0.f;
                #pragma unroll
                for (int g = 0; g < TM/4; g++) tot += h[g][tid];
                atomicAdd(&d_xg[(size_t)b*HID + tid], tot);
            }
        }
    }
}

// ------------------------------- head ---------------------------------------
__global__ void head_kernel(const float* __restrict__ f1b,
                            const float* __restrict__ fc2b,
                            const float* __restrict__ fc3w,
                            const float* __restrict__ fc3b,
                            float* __restrict__ out) {
    __shared__ float x0[HID], x1[HID], x2[HID];
    __shared__ float lg[10];
    __shared__ float lse;
    const int b = blockIdx.x;
    const int n = threadIdx.x;
    const float* f1wt  = d_Wt + 3*HID*HID;        // [k][n]
    const float* fc2wt = d_Wt + 4*HID*HID;

    x0[n] = d_xg[(size_t)b*HID + n];
    __syncthreads();

    float a = f1b[n];
    for (int k = 0; k < HID; k++) a = fmaf(f1wt[k*HID + n], x0[k], a);
    x1[n] = fmaxf(a, 0.f);
    __syncthreads();

    a = fc2b[n];
    for (int k = 0; k < HID; k++) a = fmaf(fc2wt[k*HID + n], x1[k], a);
    x2[n] = fmaxf(a, 0.f);
    __syncthreads();

    if (n < 10) {
        float l = fc3b[n];
        const float* wr = fc3w + n*HID;
        for (int k = 0; k < HID; k++) l = fmaf(wr[k], x2[k], l);
        lg[n] = l;
    }
    __syncthreads();
    if (n == 0) {
        float mx = lg[0];
        for (int c = 1; c < 10; c++) mx = fmaxf(mx, lg[c]);
        float se = 0.f;
        for (int c = 0; c < 10; c++) se += expf(lg[c] - mx);
        lse = mx + logf(se);
    }
    __syncthreads();
    if (n < 10) out[b*10 + n] = lg[n] - lse;
}

// ----------------------------- launcher --------------------------------------
extern "C" void kernel_launch(void* const* d_in, const int* in_sizes, int n_in,
                              void* d_out, int out_size) {
    const float* img  = (const float*)d_in[0];
    const float* qst  = (const float*)d_in[1];
    const float* cw1  = (const float*)d_in[2];
    const float* cb1  = (const float*)d_in[3];
    const float* bg1  = (const float*)d_in[4];
    const float* bb1  = (const float*)d_in[5];
    const float* cw2  = (const float*)d_in[6];
    const float* cb2  = (const float*)d_in[7];
    const float* bg2  = (const float*)d_in[8];
    const float* bb2  = (const float*)d_in[9];
    const float* cw3  = (const float*)d_in[10];
    const float* cb3  = (const float*)d_in[11];
    const float* bg3  = (const float*)d_in[12];
    const float* bb3  = (const float*)d_in[13];
    const float* cw4  = (const float*)d_in[14];
    const float* cb4  = (const float*)d_in[15];
    const float* bg4  = (const float*)d_in[16];
    const float* bb4  = (const float*)d_in[17];
    const float* g1w  = (const float*)d_in[18];
    const float* g1b  = (const float*)d_in[19];
    const float* g2w  = (const float*)d_in[20];
    const float* g2b  = (const float*)d_in[21];
    const float* g3w  = (const float*)d_in[22];
    const float* g3b  = (const float*)d_in[23];
    const float* g4w  = (const float*)d_in[24];
    const float* g4b  = (const float*)d_in[25];
    const float* f1w  = (const float*)d_in[26];
    const float* f1b  = (const float*)d_in[27];
    const float* fc2w = (const float*)d_in[28];
    const float* fc2b = (const float*)d_in[29];
    const float* fc3w = (const float*)d_in[30];
    const float* fc3b = (const float*)d_in[31];
    float* out = (float*)d_out;

    // symbol addresses for conv buffer chaining
    float *y1, *y2, *y3, *y4;
    cudaGetSymbolAddress((void**)&y1, d_y1);
    cudaGetSymbolAddress((void**)&y2, d_y2);
    cudaGetSymbolAddress((void**)&y3, d_y3);
    cudaGetSymbolAddress((void**)&y4, d_y4);

    zero_kernel<<<512, 256>>>();
    transpose5_kernel<<<(5*HID*HID + 255)/256, 256>>>(g2w, g3w, g4w, f1w, fc2w);

    // conv1: 3 -> 24, 80 -> 40
    conv_bn_kernel<<<dim3((NB*40*40 + 255)/256, 24), 256>>>(img, y1, cw1, cb1, 0, -1, 3, 80, 40);
    bn_finalize_kernel<<<1, 32>>>(0, 1.f/(NB*40.f*40.f), bg1, bb1);
    // conv2: 24 -> 24, 40 -> 20 (BN1 applied inline on input)
    conv_bn_kernel<<<dim3((NB*20*20 + 255)/256, 24), 256>>>(y1, y2, cw2, cb2, 1, 0, 24, 40, 20);
    bn_finalize_kernel<<<1, 32>>>(1, 1.f/(NB*20.f*20.f), bg2, bb2);
    // conv3: 20 -> 10
    conv_bn_kernel<<<dim3((NB*10*10 + 255)/256, 24), 256>>>(y2, y3, cw3, cb3, 2, 1, 24, 20, 10);
    bn_finalize_kernel<<<1, 32>>>(2, 1.f/(NB*10.f*10.f), bg3, bb3);
    // conv4: 10 -> 5
    conv_bn_kernel<<<dim3((NB*5*5 + 255)/256, 24), 256>>>(y3, y4, cw4, cb4, 3, 2, 24, 10, 5);
    bn_finalize_kernel<<<1, 32>>>(3, 1.f/(NB*5.f*5.f), bg4, bb4);

    // g1 decomposition (applies BN4 inline)
    proj_kernel<<<NB*NOBJ, 256>>>(qst, g1w, g1b);

    // fused g2/g3/g4 + pair-sum
    gmlp_kernel<<<dim3(NTILE, NB), NTHR_G>>>(g2b, g3b, g4b);

    // head + log_softmax
    head_kernel<<<NB, HID>>>(f1b, fc2b, fc3w, fc3b, out);
}

// round 4
// speedup vs baseline: 2.7381x; 2.7381x over previous
#include <cuda_runtime.h>
#include <cuda_bf16.h>
#include <math.h>
#include <stdint.h>

// ---------------------------------------------------------------------------
// RelNet forward. Convs/proj/head: fp32. g2/g3/g4: tf32 mma.sync (m16n8k8),
// fused 3-layer chain. A (activations) resident in SMEM fp32/tf32; W streamed
// in K=32 chunks via cp.async double buffer. tf32 => ~8x lower quantization
// error than the bf16 attempt (which hit 1.08e-3).
// ---------------------------------------------------------------------------

#define NB     512
#define NFS    24
#define HID    256
#define NOBJ   25
#define NPAIR  625
#define GTILES 5               // ceil(625/128)

#define PA     260             // A pitch (floats)
#define PAB    1040            // A pitch bytes
#define PW     36              // W chunk pitch (floats)
#define PWB    144
#define WBUF   36864           // 256*PW*4
#define SM_BIAS 0              // 3*256 floats
#define SM_A    3072
#define SM_W    136192         // 3072 + 128*1040 = 136192
#define SM_TOTAL 209920        // + 2*36864

// ------------------------- device scratch (static) ---------------------------
__device__ float d_y1[NB*NFS*40*40];
__device__ float d_y2[NB*NFS*20*20];
__device__ float d_y3[NB*NFS*10*10];
__device__ float d_y4[NB*NFS*25];
__device__ float d_stats[4*48];
__device__ float d_bnp[4*48];
__device__ float d_P[NB*NOBJ*HID];
__device__ float d_Q[NB*NOBJ*HID];
__device__ float d_R[NB*HID];
__device__ float d_xg[NB*HID];
__device__ float d_Wt[2*HID*HID];              // f1, fc2 transposed [k][n]
__device__ float d_Wf[3*HID*HID];              // g2,g3,g4 tf32-rounded [n][k]

// ------------------------------ helpers --------------------------------------
__device__ __forceinline__ float to_tf32(float x) {
    uint32_t r;
    asm("cvt.rna.tf32.f32 %0, %1;" : "=r"(r) : "f"(x));
    return __uint_as_float(r);
}
__device__ __forceinline__ void mma_tf32(float* c, const uint32_t* a, uint32_t b0, uint32_t b1) {
    asm volatile("mma.sync.aligned.m16n8k8.row.col.f32.tf32.tf32.f32 "
                 "{%0,%1,%2,%3}, {%4,%5,%6,%7}, {%8,%9}, {%0,%1,%2,%3};"
                 : "+f"(c[0]), "+f"(c[1]), "+f"(c[2]), "+f"(c[3])
                 : "r"(a[0]), "r"(a[1]), "r"(a[2]), "r"(a[3]), "r"(b0), "r"(b1));
}

// ------------------------------ zero init -----------------------------------
__global__ void zero_kernel() {
    int i = blockIdx.x * 256 + threadIdx.x;
    if (i < NB*HID) d_xg[i] = 0.f;
    if (i < 4*48)   d_stats[i] = 0.f;
}

// ------------- weight prep: transpose f1/fc2, tf32-round g2..g4 --------------
__global__ void prep_kernel(const float* __restrict__ g2w, const float* __restrict__ g3w,
                            const float* __restrict__ g4w, const float* __restrict__ f1w,
                            const float* __restrict__ fc2w) {
    int idx = blockIdx.x * 256 + threadIdx.x;
    if (idx < 2*HID*HID) {
        int t = idx >> 16, r = idx & 65535, k = r >> 8, n = r & 255;
        d_Wt[idx] = (t == 0 ? f1w : fc2w)[n*HID + k];
    }
    int j = idx - 2*HID*HID;
    if (j >= 0 && j < 3*HID*HID) {
        const float* s = (j < 65536) ? g2w : (j < 131072) ? g3w : g4w;
        d_Wf[j] = to_tf32(s[j & 65535]);
    }
}

// --------------------------- conv + relu + stats -----------------------------
__global__ void conv_bn_kernel(const float* __restrict__ in, float* __restrict__ out,
                               const float* __restrict__ w, const float* __restrict__ cb,
                               int stats_idx, int bn_idx,
                               int C_in, int H_in, int H_out) {
    __shared__ float ws[NFS*9];
    __shared__ float sc[NFS], sh[NFS];
    __shared__ float red1[8], red2[8];

    const int co  = blockIdx.y;
    const int tid = threadIdx.x;
    const int nw  = C_in * 9;
    for (int i = tid; i < nw; i += 256) ws[i] = w[co*nw + i];
    if (bn_idx >= 0 && tid < C_in) {
        sc[tid] = d_bnp[bn_idx*48 + tid];
        sh[tid] = d_bnp[bn_idx*48 + 24 + tid];
    }
    __syncthreads();

    const int HW    = H_out * H_out;
    const int total = NB * HW;
    const int idx   = blockIdx.x * 256 + tid;

    float y = 0.f;
    if (idx < total) {
        const int n   = idx / HW;
        const int rem = idx - n*HW;
        const int oy  = rem / H_out;
        const int ox  = rem - oy*H_out;
        float acc = cb[co];
        const float* inb = in + (size_t)n * C_in * H_in * H_in;
        for (int ci = 0; ci < C_in; ci++) {
            const float* ic = inb + ci * H_in * H_in;
            const float s = (bn_idx >= 0) ? sc[ci] : 1.f;
            const float t = (bn_idx >= 0) ? sh[ci] : 0.f;
            const float* wr = ws + ci*9;
            #pragma unroll
            for (int ky = 0; ky < 3; ky++) {
                const int iy = 2*oy - 1 + ky;
                if (iy < 0 || iy >= H_in) continue;
                #pragma unroll
                for (int kx = 0; kx < 3; kx++) {
                    const int ix = 2*ox - 1 + kx;
                    if (ix < 0 || ix >= H_in) continue;
                    acc = fmaf(wr[ky*3+kx], fmaf(ic[iy*H_in + ix], s, t), acc);
                }
            }
        }
        y = fmaxf(acc, 0.f);
        out[((size_t)n*NFS + co)*HW + rem] = y;
    }

    float v1 = y, v2 = y*y;
    #pragma unroll
    for (int off = 16; off; off >>= 1) {
        v1 += __shfl_down_sync(0xffffffffu, v1, off);
        v2 += __shfl_down_sync(0xffffffffu, v2, off);
    }
    const int wid = tid >> 5;
    if ((tid & 31) == 0) { red1[wid] = v1; red2[wid] = v2; }
    __syncthreads();
    if (tid == 0) {
        float a = 0.f, b = 0.f;
        #pragma unroll
        for (int i = 0; i < 8; i++) { a += red1[i]; b += red2[i]; }
        atomicAdd(&d_stats[stats_idx*48 + co], a);
        atomicAdd(&d_stats[stats_idx*48 + 24 + co], b);
    }
}

__global__ void bn_finalize_kernel(int layer, float inv_count,
                                   const float* __restrict__ gamma,
                                   const float* __restrict__ beta) {
    int c = threadIdx.x;
    if (c >= NFS) return;
    float mean = d_stats[layer*48 + c] * inv_count;
    float var  = d_stats[layer*48 + 24 + c] * inv_count - mean*mean;
    float s    = gamma[c] * rsqrtf(var + 1e-5f);
    d_bnp[layer*48 + c]      = s;
    d_bnp[layer*48 + 24 + c] = beta[c] - mean * s;
}

// -------------------- g1 decomposition: P, Q, R ------------------------------
__global__ void proj_kernel(const float* __restrict__ qst,
                            const float* __restrict__ g1w,
                            const float* __restrict__ g1b) {
    __shared__ float feat[26];
    const int blk = blockIdx.x;
    const int b = blk / NOBJ;
    const int o = blk - b*NOBJ;
    const int tid = threadIdx.x;

    if (tid < 24)       feat[tid] = d_y4[((size_t)b*NFS + tid)*25 + o] * d_bnp[3*48 + tid]
                                    + d_bnp[3*48 + 24 + tid];
    else if (tid == 24) feat[24] = ((float)(o / 5) - 2.f) * 0.5f;
    else if (tid == 25) feat[25] = ((float)(o % 5) - 2.f) * 0.5f;
    __syncthreads();

    const int n = tid;
    const float* wr = g1w + n*63;
    float p = 0.f, q = 0.f;
    #pragma unroll
    for (int c = 0; c < 26; c++) {
        const float f = feat[c];
        p = fmaf(wr[c],      f, p);
        q = fmaf(wr[26 + c], f, q);
    }
    d_P[((size_t)b*NOBJ + o)*HID + n] = p;
    d_Q[((size_t)b*NOBJ + o)*HID + n] = q;

    if (o == 0) {
        float r = g1b[n];
        #pragma unroll
        for (int c = 0; c < 11; c++) r = fmaf(wr[52 + c], qst[c*NB + b], r);
        d_R[(size_t)b*HID + n] = r;
    }
}

// ------------------ tf32 mma g2/g3/g4 fused MLP ------------------------------
__device__ __forceinline__ void load_Wchunk(char* smem, const float* Wlayer,
                                            int ks, int buf, int tid) {
    const float* src = Wlayer + ks*32;
    uint32_t base = 0;
    asm("{ .reg .u64 t; cvta.to.shared.u64 t, %1; cvt.u32.u64 %0, t; }"
        : "=r"(base) : "l"(smem + SM_W + buf*WBUF));
    #pragma unroll
    for (int it = 0; it < 8; it++) {
        int u = it*256 + tid;          // 0..2047 16B units
        int n = u >> 3;
        int c = u & 7;
        uint32_t dst = base + n*PWB + c*16;
        size_t gsrc = __cvta_generic_to_global(src + n*HID + c*4);
        asm volatile("cp.async.cg.shared.global [%0], [%1], 16;\n" :: "r"(dst), "l"(gsrc));
    }
    asm volatile("cp.async.commit_group;\n" ::: "memory");
}

__global__ void __launch_bounds__(256)
gmlp_tf32_kernel(const float* __restrict__ g2b, const float* __restrict__ g3b,
                 const float* __restrict__ g4b) {
    extern __shared__ char smem[];
    float* bias_s = (float*)smem;
    float* As     = (float*)(smem + SM_A);

    const int tid  = threadIdx.x;
    const int wid  = tid >> 5;
    const int lane = tid & 31;
    const int blk  = blockIdx.x;
    const int b    = blk / GTILES;
    const int t    = blk - b*GTILES;
    const int row0 = t * 128;
    const int valid = (NPAIR - row0 < 128) ? (NPAIR - row0) : 128;

    // W chunk 0 of layer 0 in flight before A build
    load_Wchunk(smem, d_Wf, 0, 0, tid);

    // stage biases
    bias_s[tid]       = g2b[tid];
    bias_s[256 + tid] = g3b[tid];
    bias_s[512 + tid] = g4b[tid];
    if (tid < 128) {
        bias_s[128 + tid]       = g2b[128 + tid];
        bias_s[256 + 128 + tid] = g3b[128 + tid];
        bias_s[512 + 128 + tid] = g4b[128 + tid];
    }

    // build A = tf32(relu(P[i] + Q[j] + R)), zero pad rows
    const float* Pb = d_P + (size_t)b*NOBJ*HID;
    const float* Qb = d_Q + (size_t)b*NOBJ*HID;
    const float* Rb = d_R + (size_t)b*HID;
    #pragma unroll 2
    for (int it = 0; it < 16; it++) {
        int v = it*256 + tid;          // 0..4095, 8 floats each
        int m = v >> 5;
        int k0 = (v & 31) * 8;
        float4 o0 = {0.f,0.f,0.f,0.f}, o1 = {0.f,0.f,0.f,0.f};
        if (m < valid) {
            int p = row0 + m;
            int j = p / NOBJ;
            int i = p - j*NOBJ;
            float4 pa = *(const float4*)(Pb + i*HID + k0);
            float4 pc = *(const float4*)(Pb + i*HID + k0 + 4);
            float4 qa = *(const float4*)(Qb + j*HID + k0);
            float4 qc = *(const float4*)(Qb + j*HID + k0 + 4);
            float4 ra = *(const float4*)(Rb + k0);
            float4 rc = *(const float4*)(Rb + k0 + 4);
            o0.x = to_tf32(fmaxf(pa.x+qa.x+ra.x, 0.f));
            o0.y = to_tf32(fmaxf(pa.y+qa.y+ra.y, 0.f));
            o0.z = to_tf32(fmaxf(pa.z+qa.z+ra.z, 0.f));
            o0.w = to_tf32(fmaxf(pa.w+qa.w+ra.w, 0.f));
            o1.x = to_tf32(fmaxf(pc.x+qc.x+rc.x, 0.f));
            o1.y = to_tf32(fmaxf(pc.y+qc.y+rc.y, 0.f));
            o1.z = to_tf32(fmaxf(pc.z+qc.z+rc.z, 0.f));
            o1.w = to_tf32(fmaxf(pc.w+qc.w+rc.w, 0.f));
        }
        *(float4*)(As + m*PA + k0)     = o0;
        *(float4*)(As + m*PA + k0 + 4) = o1;
    }

    // warp grid 2(m) x 4(n); warp tile 64x64
    const int m0 = (wid & 1) * 64;
    const int n0 = (wid >> 1) * 64;
    const int ar = m0 + (lane >> 2);
    const int ac = lane & 3;

    float acc[4][8][4];
    #pragma unroll
    for (int mi = 0; mi < 4; mi++)
        #pragma unroll
        for (int nj = 0; nj < 8; nj++)
            #pragma unroll
            for (int e = 0; e < 4; e++) acc[mi][nj][e] = 0.f;

    for (int cc = 0; cc < 24; cc++) {
        const int L   = cc >> 3;
        const int buf = cc & 1;
        asm volatile("cp.async.wait_group 0;\n" ::: "memory");
        __syncthreads();
        if (cc < 23)
            load_Wchunk(smem, d_Wf + (size_t)((cc+1) >> 3)*HID*HID, (cc+1) & 7, (cc+1) & 1, tid);

        const float* Ws = (const float*)(smem + SM_W + buf*WBUF);
        const int kbase = (cc & 7) * 32;
        #pragma unroll
        for (int kk = 0; kk < 4; kk++) {
            const int kc = kbase + kk*8 + ac;    // A col
            const int kw = kk*8 + ac;            // W col within chunk
            uint32_t a[4][4], bb[8][2];
            #pragma unroll
            for (int mi = 0; mi < 4; mi++) {
                const float* Ar = As + (ar + mi*16)*PA;
                a[mi][0] = __float_as_uint(Ar[kc]);
                a[mi][1] = __float_as_uint(Ar[8*PA + kc]);
                a[mi][2] = __float_as_uint(Ar[kc + 4]);
                a[mi][3] = __float_as_uint(Ar[8*PA + kc + 4]);
            }
            #pragma unroll
            for (int nj = 0; nj < 8; nj++) {
                const float* Wr = Ws + (n0 + nj*8 + (lane >> 2))*PW;
                bb[nj][0] = __float_as_uint(Wr[kw]);
                bb[nj][1] = __float_as_uint(Wr[kw + 4]);
            }
            #pragma unroll
            for (int mi = 0; mi < 4; mi++)
                #pragma unroll
                for (int nj = 0; nj < 8; nj++)
                    mma_tf32(acc[mi][nj], a[mi], bb[nj][0], bb[nj][1]);
        }

        if ((cc & 7) == 7) {
            __syncthreads();   // all MMA reads of A complete before rewrite
            if (L < 2) {
                const float* bl = bias_s + L*256;
                #pragma unroll
                for (int mi = 0; mi < 4; mi++) {
                    const int r0 = m0 + mi*16 + (lane >> 2);
                    #pragma unroll
                    for (int nj = 0; nj < 8; nj++) {
                        const int c0 = n0 + nj*8 + (lane & 3)*2;
                        float2 p0, p1;
                        p0.x = to_tf32(fmaxf(acc[mi][nj][0] + bl[c0],     0.f));
                        p0.y = to_tf32(fmaxf(acc[mi][nj][1] + bl[c0 + 1], 0.f));
                        p1.x = to_tf32(fmaxf(acc[mi][nj][2] + bl[c0],     0.f));
                        p1.y = to_tf32(fmaxf(acc[mi][nj][3] + bl[c0 + 1], 0.f));
                        *(float2*)(As + r0*PA + c0)       = p0;
                        *(float2*)(As + (r0 + 8)*PA + c0) = p1;
                        acc[mi][nj][0] = 0.f; acc[mi][nj][1] = 0.f;
                        acc[mi][nj][2] = 0.f; acc[mi][nj][3] = 0.f;
                    }
                }
            } else {
                // final layer: masked column sums + atomics
                const float* bl = bias_s + 512;
                #pragma unroll
                for (int nj = 0; nj < 8; nj++) {
                    const int c0 = n0 + nj*8 + (lane & 3)*2;
                    float v0 = 0.f, v1 = 0.f;
                    #pragma unroll
                    for (int mi = 0; mi < 4; mi++) {
                        const int ra = m0 + mi*16 + (lane >> 2);
                        if (ra < valid) {
                            v0 += fmaxf(acc[mi][nj][0] + bl[c0],     0.f);
                            v1 += fmaxf(acc[mi][nj][1] + bl[c0 + 1], 0.f);
                        }
                        if (ra + 8 < valid) {
                            v0 += fmaxf(acc[mi][nj][2] + bl[c0],     0.f);
                            v1 += fmaxf(acc[mi][nj][3] + bl[c0 + 1], 0.f);
                        }
                    }
                    #pragma unroll
                    for (int off = 4; off < 32; off <<= 1) {
                        v0 += __shfl_xor_sync(0xffffffffu, v0, off);
                        v1 += __shfl_xor_sync(0xffffffffu, v1, off);
                    }
                    if (lane < 4) {
                        atomicAdd(&d_xg[(size_t)b*HID + c0],     v0);
                        atomicAdd(&d_xg[(size_t)b*HID + c0 + 1], v1);
                    }
                }
            }
        }
    }
}

// ------------------------------- head ---------------------------------------
__global__ void head_kernel(const float* __restrict__ f1b,
                            const float* __restrict__ fc2b,
                            const float* __restrict__ fc3w,
                            const float* __restrict__ fc3b,
                            float* __restrict__ out) {
    __shared__ float x0[HID], x1[HID], x2[HID];
    __shared__ float lg[10];
    __shared__ float lse;
    const int b = blockIdx.x;
    const int n = threadIdx.x;
    const float* f1wt  = d_Wt;                  // [k][n]
    const float* fc2wt = d_Wt + HID*HID;

    x0[n] = d_xg[(size_t)b*HID + n];
    __syncthreads();

    float a = f1b[n];
    for (int k = 0; k < HID; k++) a = fmaf(f1wt[k*HID + n], x0[k], a);
    x1[n] = fmaxf(a, 0.f);
    __syncthreads();

    a = fc2b[n];
    for (int k = 0; k < HID; k++) a = fmaf(fc2wt[k*HID + n], x1[k], a);
    x2[n] = fmaxf(a, 0.f);
    __syncthreads();

    if (n < 10) {
        float l = fc3b[n];
        const float* wr = fc3w + n*HID;
        for (int k = 0; k < HID; k++) l = fmaf(wr[k], x2[k], l);
        lg[n] = l;
    }
    __syncthreads();
    if (n == 0) {
        float mx = lg[0];
        for (int c = 1; c < 10; c++) mx = fmaxf(mx, lg[c]);
        float se = 0.f;
        for (int c = 0; c < 10; c++) se += expf(lg[c] - mx);
        lse = mx + logf(se);
    }
    __syncthreads();
    if (n < 10) out[b*10 + n] = lg[n] - lse;
}

// ----------------------------- launcher --------------------------------------
extern "C" void kernel_launch(void* const* d_in, const int* in_sizes, int n_in,
                              void* d_out, int out_size) {
    const float* img  = (const float*)d_in[0];
    const float* qst  = (const float*)d_in[1];
    const float* cw1  = (const float*)d_in[2];
    const float* cb1  = (const float*)d_in[3];
    const float* bg1  = (const float*)d_in[4];
    const float* bb1  = (const float*)d_in[5];
    const float* cw2  = (const float*)d_in[6];
    const float* cb2  = (const float*)d_in[7];
    const float* bg2  = (const float*)d_in[8];
    const float* bb2  = (const float*)d_in[9];
    const float* cw3  = (const float*)d_in[10];
    const float* cb3  = (const float*)d_in[11];
    const float* bg3  = (const float*)d_in[12];
    const float* bb3  = (const float*)d_in[13];
    const float* cw4  = (const float*)d_in[14];
    const float* cb4  = (const float*)d_in[15];
    const float* bg4  = (const float*)d_in[16];
    const float* bb4  = (const float*)d_in[17];
    const float* g1w  = (const float*)d_in[18];
    const float* g1b  = (const float*)d_in[19];
    const float* g2w  = (const float*)d_in[20];
    const float* g2b  = (const float*)d_in[21];
    const float* g3w  = (const float*)d_in[22];
    const float* g3b  = (const float*)d_in[23];
    const float* g4w  = (const float*)d_in[24];
    const float* g4b  = (const float*)d_in[25];
    const float* f1w  = (const float*)d_in[26];
    const float* f1b  = (const float*)d_in[27];
    const float* fc2w = (const float*)d_in[28];
    const float* fc2b = (const float*)d_in[29];
    const float* fc3w = (const float*)d_in[30];
    const float* fc3b = (const float*)d_in[31];
    float* out = (float*)d_out;

    float *y1, *y2, *y3, *y4;
    cudaGetSymbolAddress((void**)&y1, d_y1);
    cudaGetSymbolAddress((void**)&y2, d_y2);
    cudaGetSymbolAddress((void**)&y3, d_y3);
    cudaGetSymbolAddress((void**)&y4, d_y4);

    cudaFuncSetAttribute(gmlp_tf32_kernel, cudaFuncAttributeMaxDynamicSharedMemorySize, SM_TOTAL);

    zero_kernel<<<512, 256>>>();
    prep_kernel<<<(5*HID*HID + 255)/256, 256>>>(g2w, g3w, g4w, f1w, fc2w);

    conv_bn_kernel<<<dim3((NB*40*40 + 255)/256, 24), 256>>>(img, y1, cw1, cb1, 0, -1, 3, 80, 40);
    bn_finalize_kernel<<<1, 32>>>(0, 1.f/(NB*40.f*40.f), bg1, bb1);
    conv_bn_kernel<<<dim3((NB*20*20 + 255)/256, 24), 256>>>(y1, y2, cw2, cb2, 1, 0, 24, 40, 20);
    bn_finalize_kernel<<<1, 32>>>(1, 1.f/(NB*20.f*20.f), bg2, bb2);
    conv_bn_kernel<<<dim3((NB*10*10 + 255)/256, 24), 256>>>(y2, y3, cw3, cb3, 2, 1, 24, 20, 10);
    bn_finalize_kernel<<<1, 32>>>(2, 1.f/(NB*10.f*10.f), bg3, bb3);
    conv_bn_kernel<<<dim3((NB*5*5 + 255)/256, 24), 256>>>(y3, y4, cw4, cb4, 3, 2, 24, 10, 5);
    bn_finalize_kernel<<<1, 32>>>(3, 1.f/(NB*5.f*5.f), bg4, bb4);

    proj_kernel<<<NB*NOBJ, 256>>>(qst, g1w, g1b);

    gmlp_tf32_kernel<<<NB*GTILES, 256, SM_TOTAL>>>(g2b, g3b, g4b);

    head_kernel<<<NB, HID>>>(f1b, fc2b, fc3w, fc3b, out);
}

// round 5
// speedup vs baseline: 6.0683x; 2.2163x over previous
#include <cuda_runtime.h>
#include <cuda_fp16.h>
#include <math.h>
#include <stdint.h>

// ---------------------------------------------------------------------------
// RelNet forward.
//   convs: smem-tiled direct conv + relu + batch-stat BN folded into consumer.
//   g1:    decomposed P/Q/R (stored fp16), weights pre-transposed (coalesced).
//   g2-g4: fp16 mma.sync m16n8k16 fused 3-layer chain, ldmatrix fragments,
//          W layer resident in smem via cp.async (port of verified bf16 rd-3).
//   head:  4 batches per block, fp32.
// ---------------------------------------------------------------------------

#define NB     512
#define NFS    24
#define HID    256
#define NOBJ   25
#define NPAIR  625
#define GTILES 5               // ceil(625/128)

#define LDAB   528             // gmlp smem row pitch bytes (264 halves)
#define SM_BIAS 0              // 3*256 floats = 3072 B
#define SM_H    3072           // 128 x 528
#define SM_W    70656          // 256 x 528
#define SM_TOTAL 205824

// conv234 dynamic smem layout (floats)
#define CT_TILE 0              // 24*441
#define CT_WS   10584          // 24*217
#define CT_P1   15792          // 256
#define CT_P2   16048          // 256
#define CT_SC   16304          // 24
#define CT_SH   16328          // 24
#define CT_FLOATS 16352
#define CT_BYTES  65408

// ------------------------- device scratch (static) ---------------------------
__device__ float d_y1[NB*NFS*40*40];
__device__ float d_y2[NB*NFS*20*20];
__device__ float d_y3[NB*NFS*10*10];
__device__ float d_y4[NB*NFS*25];
__device__ float d_stats[4*48];
__device__ float d_bnp[4*48];
__device__ __align__(16) __half d_P[NB*NOBJ*HID];
__device__ __align__(16) __half d_Q[NB*NOBJ*HID];
__device__ __align__(16) __half d_R[NB*HID];
__device__ float d_xg[NB*HID];
__device__ float d_Wt[2*HID*HID];               // f1, fc2 transposed [k][n]
__device__ __align__(16) __half d_Wh[3*HID*HID];// g2,g3,g4 fp16 [n][k]
__device__ float d_g1t[63*HID];                 // g1w transposed [c][n]

// ------------------------------ helpers --------------------------------------
__device__ __forceinline__ uint32_t smem_u32(const void* p) {
    uint32_t a;
    asm("{ .reg .u64 t; cvta.to.shared.u64 t, %1; cvt.u32.u64 %0, t; }" : "=r"(a) : "l"(p));
    return a;
}
__device__ __forceinline__ void ldsm_x4(uint32_t* r, uint32_t addr) {
    asm volatile("ldmatrix.sync.aligned.m8n8.x4.shared.b16 {%0,%1,%2,%3}, [%4];"
                 : "=r"(r[0]), "=r"(r[1]), "=r"(r[2]), "=r"(r[3]) : "r"(addr));
}
__device__ __forceinline__ void mma16816(float* c, const uint32_t* a, uint32_t b0, uint32_t b1) {
    asm volatile("mma.sync.aligned.m16n8k16.row.col.f32.f16.f16.f32 "
                 "{%0,%1,%2,%3}, {%4,%5,%6,%7}, {%8,%9}, {%0,%1,%2,%3};"
                 : "+f"(c[0]), "+f"(c[1]), "+f"(c[2]), "+f"(c[3])
                 : "r"(a[0]), "r"(a[1]), "r"(a[2]), "r"(a[3]), "r"(b0), "r"(b1));
}
__device__ __forceinline__ uint32_t h2relu3(uint32_t a, uint32_t b, uint32_t c) {
    __half2 z = __float2half2_rn(0.f);
    __half2 r = __hmax2(__hadd2(__hadd2(*(__half2*)&a, *(__half2*)&b), *(__half2*)&c), z);
    return *(uint32_t*)&r;
}

// ------------------------------ zero init -----------------------------------
__global__ void zero_kernel() {
    int i = blockIdx.x * 256 + threadIdx.x;
    if (i < NB*HID) d_xg[i] = 0.f;
    if (i < 4*48)   d_stats[i] = 0.f;
}

// ------------- weight prep: transpose f1/fc2, fp16 g2..g4 --------------------
__global__ void prep_kernel(const float* __restrict__ g2w, const float* __restrict__ g3w,
                            const float* __restrict__ g4w, const float* __restrict__ f1w,
                            const float* __restrict__ fc2w) {
    int idx = blockIdx.x * 256 + threadIdx.x;
    if (idx < 2*HID*HID) {
        int t = idx >> 16, r = idx & 65535, k = r >> 8, n = r & 255;
        d_Wt[idx] = (t == 0 ? f1w : fc2w)[n*HID + k];
    }
    int j = idx - 2*HID*HID;
    if (j >= 0 && j < 3*HID*HID) {
        const float* s = (j < 65536) ? g2w : (j < 131072) ? g3w : g4w;
        d_Wh[j] = __float2half(s[j & 65535]);
    }
}

__global__ void g1t_kernel(const float* __restrict__ g1w) {
    int idx = blockIdx.x * 256 + threadIdx.x;
    if (idx < 63*HID) {
        int c = idx >> 8, n = idx & 255;
        d_g1t[idx] = g1w[n*63 + c];
    }
}

// --------------------------- conv1 (3ch, 80->40), tiled ----------------------
__global__ void __launch_bounds__(512)
conv1_kernel(const float* __restrict__ img, float* __restrict__ out,
             const float* __restrict__ w, const float* __restrict__ cb) {
    __shared__ float tile[3*41*41];
    __shared__ float ws[24*27];
    __shared__ float p1[512], p2[512];

    const int n   = blockIdx.y;
    const int bx  = blockIdx.x;          // 0..3
    const int ty  = bx >> 1, tx = bx & 1;
    const int oy0 = ty*20, ox0 = tx*20;
    const int tid = threadIdx.x;

    for (int i = tid; i < 648; i += 512) ws[i] = w[i];
    const int iy0 = oy0*2 - 1, ix0 = ox0*2 - 1;
    for (int e = tid; e < 3*41*41; e += 512) {
        int ci = e / 1681, r = e % 1681;
        int ly = r / 41, lx = r % 41;
        int iy = iy0 + ly, ix = ix0 + lx;
        float v = (iy >= 0 && iy < 80 && ix >= 0 && ix < 80)
                  ? img[((size_t)n*3 + ci)*6400 + iy*80 + ix] : 0.f;
        tile[e] = v;
    }
    __syncthreads();

    float s1 = 0.f, s2 = 0.f;
    if (tid < 480) {
        const int co = tid / 20, r = tid % 20;
        float acc[20];
        const float bias = cb[co];
        #pragma unroll
        for (int c = 0; c < 20; c++) acc[c] = bias;
        #pragma unroll
        for (int ci = 0; ci < 3; ci++) {
            const float* wr = ws + co*27 + ci*9;
            const float* tb = tile + ci*1681;
            #pragma unroll
            for (int ky = 0; ky < 3; ky++) {
                const float* row = tb + (2*r + ky)*41;
                float rv[41];
                #pragma unroll
                for (int i = 0; i < 41; i++) rv[i] = row[i];
                const float w0 = wr[ky*3], w1 = wr[ky*3+1], w2 = wr[ky*3+2];
                #pragma unroll
                for (int c = 0; c < 20; c++)
                    acc[c] = fmaf(rv[2*c], w0, fmaf(rv[2*c+1], w1, fmaf(rv[2*c+2], w2, acc[c])));
            }
        }
        const int oy = oy0 + r;
        float* orow = out + ((size_t)n*24 + co)*1600 + oy*40 + ox0;
        #pragma unroll
        for (int c = 0; c < 20; c++) {
            float y = fmaxf(acc[c], 0.f);
            orow[c] = y;
            s1 += y; s2 += y*y;
        }
    }
    p1[tid] = s1; p2[tid] = s2;
    __syncthreads();
    if (tid < 48) {
        const int co = tid % 24, st = tid / 24;
        const float* p = st ? p2 : p1;
        float s = 0.f;
        #pragma unroll
        for (int i = 0; i < 20; i++) s += p[co*20 + i];
        atomicAdd(&d_stats[st*24 + co], s);
    }
}

// ----------------- conv2/3/4 (24ch in/out), tiled, BN on input ---------------
__global__ void __launch_bounds__(256)
conv234_kernel(const float* __restrict__ in, float* __restrict__ out,
               const float* __restrict__ w, const float* __restrict__ cb,
               int stats_idx, int H_in, int H_out) {
    extern __shared__ float dsm[];
    float* tile = dsm + CT_TILE;
    float* ws   = dsm + CT_WS;
    float* p1   = dsm + CT_P1;
    float* p2   = dsm + CT_P2;
    float* sc   = dsm + CT_SC;
    float* sh   = dsm + CT_SH;

    const int n   = blockIdx.y;
    const int bx  = blockIdx.x;
    const int tps = (gridDim.x == 4) ? 2 : 1;
    const int ty  = bx / tps, tx = bx % tps;
    const int oy0 = ty*10, ox0 = tx*10;
    const int tid = threadIdx.x;
    const int bn  = stats_idx - 1;

    if (tid < 24) {
        sc[tid] = d_bnp[bn*48 + tid];
        sh[tid] = d_bnp[bn*48 + 24 + tid];
    }
    for (int i = tid; i < 5184; i += 256) {
        int co = i / 216;
        ws[co*217 + (i - co*216)] = w[i];
    }
    __syncthreads();

    const int HWin = H_in * H_in;
    const int iy0 = oy0*2 - 1, ix0 = ox0*2 - 1;
    for (int e = tid; e < 24*441; e += 256) {
        int ci = e / 441, r = e % 441;
        int ly = r / 21, lx = r % 21;
        int iy = iy0 + ly, ix = ix0 + lx;
        float v = 0.f;
        if (iy >= 0 && iy < H_in && ix >= 0 && ix < H_in)
            v = fmaf(in[((size_t)n*24 + ci)*HWin + iy*H_in + ix], sc[ci], sh[ci]);
        tile[e] = v;
    }
    __syncthreads();

    float s1 = 0.f, s2 = 0.f;
    if (tid < 240) {
        const int co = tid / 10, r = tid % 10;
        const int oy = oy0 + r;
        float acc[10];
        const float bias = cb[co];
        #pragma unroll
        for (int c = 0; c < 10; c++) acc[c] = bias;
        #pragma unroll 4
        for (int ci = 0; ci < 24; ci++) {
            const float* wr = ws + co*217 + ci*9;
            float wv[9];
            #pragma unroll
            for (int k = 0; k < 9; k++) wv[k] = wr[k];
            const float* tb = tile + ci*441;
            #pragma unroll
            for (int ky = 0; ky < 3; ky++) {
                const float* row = tb + (2*r + ky)*21;
                float rv[21];
                #pragma unroll
                for (int i = 0; i < 21; i++) rv[i] = row[i];
                #pragma unroll
                for (int c = 0; c < 10; c++)
                    acc[c] = fmaf(rv[2*c], wv[ky*3], fmaf(rv[2*c+1], wv[ky*3+1],
                              fmaf(rv[2*c+2], wv[ky*3+2], acc[c])));
            }
        }
        if (oy < H_out) {
            float* orow = out + ((size_t)n*24 + co)*H_out*H_out + oy*H_out + ox0;
            #pragma unroll
            for (int c = 0; c < 10; c++) {
                if (ox0 + c < H_out) {
                    float y = fmaxf(acc[c], 0.f);
                    orow[c] = y;
                    s1 += y; s2 += y*y;
                }
            }
        }
    }
    p1[tid] = s1; p2[tid] = s2;
    __syncthreads();
    if (tid < 48) {
        const int co = tid % 24, st = tid / 24;
        const float* p = st ? p2 : p1;
        float s = 0.f;
        #pragma unroll
        for (int i = 0; i < 10; i++) s += p[co*10 + i];
        atomicAdd(&d_stats[stats_idx*48 + st*24 + co], s);
    }
}

__global__ void bn_finalize_kernel(int layer, float inv_count,
                                   const float* __restrict__ gamma,
                                   const float* __restrict__ beta) {
    int c = threadIdx.x;
    if (c >= NFS) return;
    float mean = d_stats[layer*48 + c] * inv_count;
    float var  = d_stats[layer*48 + 24 + c] * inv_count - mean*mean;
    float s    = gamma[c] * rsqrtf(var + 1e-5f);
    d_bnp[layer*48 + c]      = s;
    d_bnp[layer*48 + 24 + c] = beta[c] - mean * s;
}

// -------------------- g1 decomposition: P, Q, R (fp16 out) -------------------
__global__ void proj_kernel(const float* __restrict__ qst,
                            const float* __restrict__ g1b) {
    __shared__ float feat[26];
    const int blk = blockIdx.x;
    const int b = blk / NOBJ;
    const int o = blk - b*NOBJ;
    const int tid = threadIdx.x;

    if (tid < 24)       feat[tid] = d_y4[((size_t)b*NFS + tid)*25 + o] * d_bnp[3*48 + tid]
                                    + d_bnp[3*48 + 24 + tid];
    else if (tid == 24) feat[24] = ((float)(o / 5) - 2.f) * 0.5f;
    else if (tid == 25) feat[25] = ((float)(o % 5) - 2.f) * 0.5f;
    __syncthreads();

    const int n = tid;
    float p = 0.f, q = 0.f;
    #pragma unroll
    for (int c = 0; c < 26; c++) {
        const float f = feat[c];
        p = fmaf(d_g1t[c*HID + n],        f, p);
        q = fmaf(d_g1t[(26 + c)*HID + n], f, q);
    }
    d_P[((size_t)b*NOBJ + o)*HID + n] = __float2half(p);
    d_Q[((size_t)b*NOBJ + o)*HID + n] = __float2half(q);

    if (o == 0) {
        float r = g1b[n];
        #pragma unroll
        for (int c = 0; c < 11; c++) r = fmaf(d_g1t[(52 + c)*HID + n], qst[c*NB + b], r);
        d_R[(size_t)b*HID + n] = __float2half(r);
    }
}

// ------------------ fp16 mma g2/g3/g4 fused MLP ------------------------------
__device__ __forceinline__ void load_W_async(uint32_t sb, const __half* W, int tid) {
    #pragma unroll 8
    for (int it = 0; it < 32; it++) {
        int idx = it*256 + tid;        // 0..8191 16B chunks
        int n = idx >> 5;
        int c = idx & 31;
        uint32_t dst = sb + SM_W + n*LDAB + c*16;
        size_t src = __cvta_generic_to_global((const char*)(W + n*HID) + c*16);
        asm volatile("cp.async.cg.shared.global [%0], [%1], 16;\n" :: "r"(dst), "l"(src));
    }
    asm volatile("cp.async.commit_group;\n" ::: "memory");
}

__global__ void __launch_bounds__(256, 1)
gmlp_mma_kernel(const float* __restrict__ g2b, const float* __restrict__ g3b,
                const float* __restrict__ g4b) {
    extern __shared__ char smem[];
    const uint32_t sb = smem_u32(smem);
    float* bias_s = (float*)smem;       // [3][256]

    const int tid  = threadIdx.x;
    const int wid  = tid >> 5;
    const int lane = tid & 31;
    const int blk  = blockIdx.x;
    const int b    = blk / GTILES;
    const int t    = blk - b*GTILES;
    const int row0 = t * 128;
    const int valid = (NPAIR - row0 < 128) ? (NPAIR - row0) : 128;

    load_W_async(sb, d_Wh, tid);        // layer-0 W in flight

    bias_s[tid]       = g2b[tid];
    bias_s[256 + tid] = g3b[tid];
    bias_s[512 + tid] = g4b[tid];
    if (tid < 128) {
        bias_s[128 + tid]       = g2b[128 + tid];
        bias_s[256 + 128 + tid] = g3b[128 + tid];
        bias_s[512 + 128 + tid] = g4b[128 + tid];
    }

    // build h = relu(P[i] + Q[j] + R) in fp16, zero pad rows
    const __half* Ph = d_P + (size_t)b*NOBJ*HID;
    const __half* Qh = d_Q + (size_t)b*NOBJ*HID;
    const __half* Rh = d_R + (size_t)b*HID;
    #pragma unroll 4
    for (int it = 0; it < 16; it++) {
        int v = it*256 + tid;          // 0..4095, 8 halves each
        int m = v >> 5;
        int u = v & 31;                // 16B unit
        int k0 = u * 8;
        uint4 o = {0u, 0u, 0u, 0u};
        if (m < valid) {
            int p = row0 + m;
            int j = p / NOBJ;
            int i = p - j*NOBJ;
            uint4 P4 = *(const uint4*)(Ph + i*HID + k0);
            uint4 Q4 = *(const uint4*)(Qh + j*HID + k0);
            uint4 R4 = *(const uint4*)(Rh + k0);
            o.x = h2relu3(P4.x, Q4.x, R4.x);
            o.y = h2relu3(P4.y, Q4.y, R4.y);
            o.z = h2relu3(P4.z, Q4.z, R4.z);
            o.w = h2relu3(P4.w, Q4.w, R4.w);
        }
        uint32_t addr = sb + SM_H + m*LDAB + u*16;
        asm volatile("st.shared.v4.b32 [%0], {%1,%2,%3,%4};" :: "r"(addr),
                     "r"(o.x), "r"(o.y), "r"(o.z), "r"(o.w));
    }
    asm volatile("cp.async.wait_group 0;\n" ::: "memory");
    __syncthreads();

    // warp grid: 2(m) x 4(n); warp tile 64x64
    const int m0 = (wid & 1) * 64;
    const int n0 = (wid >> 1) * 64;
    const uint32_t aAddr0 = sb + SM_H + (m0 + (lane & 15))*LDAB + (8*(lane >> 4))*2;
    const uint32_t bAddr0 = sb + SM_W + (n0 + (lane & 7) + (lane >> 4)*8)*LDAB
                                       + (((lane >> 3) & 1)*8)*2;

    for (int L = 0; L < 3; L++) {
        float acc[4][8][4];
        #pragma unroll
        for (int mi = 0; mi < 4; mi++)
            #pragma unroll
            for (int nj = 0; nj < 8; nj++)
                #pragma unroll
                for (int e = 0; e < 4; e++) acc[mi][nj][e] = 0.f;

        #pragma unroll 1
        for (int ks = 0; ks < 16; ks++) {
            const uint32_t koff = ks * 32;   // 16 halves
            uint32_t a[4][4], bfr[4][4];
            #pragma unroll
            for (int mi = 0; mi < 4; mi++)
                ldsm_x4(a[mi], aAddr0 + mi*16*LDAB + koff);
            #pragma unroll
            for (int nt = 0; nt < 4; nt++)
                ldsm_x4(bfr[nt], bAddr0 + nt*16*LDAB + koff);
            #pragma unroll
            for (int mi = 0; mi < 4; mi++)
                #pragma unroll
                for (int nt = 0; nt < 4; nt++) {
                    mma16816(acc[mi][nt*2],     a[mi], bfr[nt][0], bfr[nt][1]);
                    mma16816(acc[mi][nt*2 + 1], a[mi], bfr[nt][2], bfr[nt][3]);
                }
        }
        __syncthreads();   // all reads of h and W complete

        if (L < 2) {
            load_W_async(sb, d_Wh + (size_t)(L+1)*HID*HID, tid);  // overlap epilogue
            const float* bl = bias_s + L*256;
            #pragma unroll
            for (int mi = 0; mi < 4; mi++) {
                const int r0 = m0 + mi*16 + lane/4;
                #pragma unroll
                for (int nj = 0; nj < 8; nj++) {
                    const int c0 = n0 + nj*8 + (lane & 3)*2;
                    __half2 q0 = __floats2half2_rn(
                        fmaxf(acc[mi][nj][0] + bl[c0],     0.f),
                        fmaxf(acc[mi][nj][1] + bl[c0 + 1], 0.f));
                    __half2 q1 = __floats2half2_rn(
                        fmaxf(acc[mi][nj][2] + bl[c0],     0.f),
                        fmaxf(acc[mi][nj][3] + bl[c0 + 1], 0.f));
                    *(uint32_t*)(smem + SM_H + r0*LDAB + c0*2)       = *(uint32_t*)&q0;
                    *(uint32_t*)(smem + SM_H + (r0 + 8)*LDAB + c0*2) = *(uint32_t*)&q1;
                }
            }
            asm volatile("cp.async.wait_group 0;\n" ::: "memory");
            __syncthreads();
        } else {
            const float* bl = bias_s + 512;
            #pragma unroll
            for (int nj = 0; nj < 8; nj++) {
                const int c0 = n0 + nj*8 + (lane & 3)*2;
                float v0 = 0.f, v1 = 0.f;
                #pragma unroll
                for (int mi = 0; mi < 4; mi++) {
                    const int ra = m0 + mi*16 + lane/4;
                    if (ra < valid) {
                        v0 += fmaxf(acc[mi][nj][0] + bl[c0],     0.f);
                        v1 += fmaxf(acc[mi][nj][1] + bl[c0 + 1], 0.f);
                    }
                    if (ra + 8 < valid) {
                        v0 += fmaxf(acc[mi][nj][2] + bl[c0],     0.f);
                        v1 += fmaxf(acc[mi][nj][3] + bl[c0 + 1], 0.f);
                    }
                }
                #pragma unroll
                for (int off = 4; off < 32; off <<= 1) {
                    v0 += __shfl_xor_sync(0xffffffffu, v0, off);
                    v1 += __shfl_xor_sync(0xffffffffu, v1, off);
                }
                if (lane < 4) {
                    atomicAdd(&d_xg[(size_t)b*HID + c0],     v0);
                    atomicAdd(&d_xg[(size_t)b*HID + c0 + 1], v1);
                }
            }
        }
    }
}

// ------------------------------- head (4 batches/block) ----------------------
__global__ void __launch_bounds__(256)
head_kernel(const float* __restrict__ f1b, const float* __restrict__ fc2b,
            const float* __restrict__ fc3w, const float* __restrict__ fc3b,
            float* __restrict__ out) {
    __shared__ float xa[4][HID], xb[4][HID];
    __shared__ float lg[4][10];
    const int b0 = blockIdx.x * 4;
    const int n  = threadIdx.x;
    const float* f1wt  = d_Wt;
    const float* fc2wt = d_Wt + HID*HID;

    #pragma unroll
    for (int bi = 0; bi < 4; bi++) xa[bi][n] = d_xg[(size_t)(b0 + bi)*HID + n];
    __syncthreads();

    float a0, a1, a2, a3;
    a0 = a1 = a2 = a3 = f1b[n];
    for (int k = 0; k < HID; k++) {
        const float w = f1wt[k*HID + n];
        a0 = fmaf(w, xa[0][k], a0); a1 = fmaf(w, xa[1][k], a1);
        a2 = fmaf(w, xa[2][k], a2); a3 = fmaf(w, xa[3][k], a3);
    }
    xb[0][n] = fmaxf(a0, 0.f); xb[1][n] = fmaxf(a1, 0.f);
    xb[2][n] = fmaxf(a2, 0.f); xb[3][n] = fmaxf(a3, 0.f);
    __syncthreads();

    a0 = a1 = a2 = a3 = fc2b[n];
    for (int k = 0; k < HID; k++) {
        const float w = fc2wt[k*HID + n];
        a0 = fmaf(w, xb[0][k], a0); a1 = fmaf(w, xb[1][k], a1);
        a2 = fmaf(w, xb[2][k], a2); a3 = fmaf(w, xb[3][k], a3);
    }
    xa[0][n] = fmaxf(a0, 0.f); xa[1][n] = fmaxf(a1, 0.f);
    xa[2][n] = fmaxf(a2, 0.f); xa[3][n] = fmaxf(a3, 0.f);
    __syncthreads();

    if (n < 40) {
        const int co = n % 10, bi = n / 10;
        float l = fc3b[co];
        const float* wr = fc3w + co*HID;
        for (int k = 0; k < HID; k++) l = fmaf(wr[k], xa[bi][k], l);
        lg[bi][co] = l;
    }
    __syncthreads();
    if (n < 4) {
        float mx = lg[n][0];
        #pragma unroll
        for (int c = 1; c < 10; c++) mx = fmaxf(mx, lg[n][c]);
        float se = 0.f;
        #pragma unroll
        for (int c = 0; c < 10; c++) se += expf(lg[n][c] - mx);
        const float lse = mx + logf(se);
        #pragma unroll
        for (int c = 0; c < 10; c++) out[(b0 + n)*10 + c] = lg[n][c] - lse;
    }
}

// ----------------------------- launcher --------------------------------------
extern "C" void kernel_launch(void* const* d_in, const int* in_sizes, int n_in,
                              void* d_out, int out_size) {
    const float* img  = (const float*)d_in[0];
    const float* qst  = (const float*)d_in[1];
    const float* cw1  = (const float*)d_in[2];
    const float* cb1  = (const float*)d_in[3];
    const float* bg1  = (const float*)d_in[4];
    const float* bb1  = (const float*)d_in[5];
    const float* cw2  = (const float*)d_in[6];
    const float* cb2  = (const float*)d_in[7];
    const float* bg2  = (const float*)d_in[8];
    const float* bb2  = (const float*)d_in[9];
    const float* cw3  = (const float*)d_in[10];
    const float* cb3  = (const float*)d_in[11];
    const float* bg3  = (const float*)d_in[12];
    const float* bb3  = (const float*)d_in[13];
    const float* cw4  = (const float*)d_in[14];
    const float* cb4  = (const float*)d_in[15];
    const float* bg4  = (const float*)d_in[16];
    const float* bb4  = (const float*)d_in[17];
    const float* g1w  = (const float*)d_in[18];
    const float* g1b  = (const float*)d_in[19];
    const float* g2w  = (const float*)d_in[20];
    const float* g2b  = (const float*)d_in[21];
    const float* g3w  = (const float*)d_in[22];
    const float* g3b  = (const float*)d_in[23];
    const float* g4w  = (const float*)d_in[24];
    const float* g4b  = (const float*)d_in[25];
    const float* f1w  = (const float*)d_in[26];
    const float* f1b  = (const float*)d_in[27];
    const float* fc2w = (const float*)d_in[28];
    const float* fc2b = (const float*)d_in[29];
    const float* fc3w = (const float*)d_in[30];
    const float* fc3b = (const float*)d_in[31];
    float* out = (float*)d_out;

    float *y1, *y2, *y3, *y4;
    cudaGetSymbolAddress((void**)&y1, d_y1);
    cudaGetSymbolAddress((void**)&y2, d_y2);
    cudaGetSymbolAddress((void**)&y3, d_y3);
    cudaGetSymbolAddress((void**)&y4, d_y4);

    cudaFuncSetAttribute(gmlp_mma_kernel, cudaFuncAttributeMaxDynamicSharedMemorySize, SM_TOTAL);
    cudaFuncSetAttribute(conv234_kernel, cudaFuncAttributeMaxDynamicSharedMemorySize, CT_BYTES);

    zero_kernel<<<512, 256>>>();
    prep_kernel<<<(5*HID*HID + 255)/256, 256>>>(g2w, g3w, g4w, f1w, fc2w);
    g1t_kernel<<<63, 256>>>(g1w);

    conv1_kernel<<<dim3(4, NB), 512>>>(img, y1, cw1, cb1);
    bn_finalize_kernel<<<1, 32>>>(0, 1.f/(NB*40.f*40.f), bg1, bb1);
    conv234_kernel<<<dim3(4, NB), 256, CT_BYTES>>>(y1, y2, cw2, cb2, 1, 40, 20);
    bn_finalize_kernel<<<1, 32>>>(1, 1.f/(NB*20.f*20.f), bg2, bb2);
    conv234_kernel<<<dim3(1, NB), 256, CT_BYTES>>>(y2, y3, cw3, cb3, 2, 20, 10);
    bn_finalize_kernel<<<1, 32>>>(2, 1.f/(NB*10.f*10.f), bg3, bb3);
    conv234_kernel<<<dim3(1, NB), 256, CT_BYTES>>>(y3, y4, cw4, cb4, 3, 10, 5);
    bn_finalize_kernel<<<1, 32>>>(3, 1.f/(NB*5.f*5.f), bg4, bb4);

    proj_kernel<<<NB*NOBJ, 256>>>(qst, g1b);

    gmlp_mma_kernel<<<NB*GTILES, 256, SM_TOTAL>>>(g2b, g3b, g4b);

    head_kernel<<<NB/4, 256>>>(f1b, fc2b, fc3w, fc3b, out);
}

// round 7
// speedup vs baseline: 6.3650x; 1.0489x over previous
#include <cuda_runtime.h>
#include <cuda_fp16.h>
#include <math.h>
#include <stdint.h>

// ---------------------------------------------------------------------------
// RelNet forward.
//   convs: register-blocked tiled direct conv (4co or 2co per thread, float4
//          smem window loads), relu, batch stats; BN folded into consumer
//          (each consumer CTA derives scale/shift from d_stats directly).
//   g1:    per-batch proj, weights register-resident, P/Q/R fp16.
//   g2-g4: fp16 mma.sync m16n8k16 fused 3-layer chain (unchanged, verified).
//   head:  8 batches per block.
// ---------------------------------------------------------------------------

#define NB     512
#define NFS    24
#define HID    256
#define NOBJ   25
#define NPAIR  625
#define GTILES 5

#define LDAB   528
#define SM_H    3072
#define SM_W    70656
#define SM_TOTAL 205824

// ------------------------- device scratch (static) ---------------------------
__device__ float d_y1[NB*NFS*40*40];
__device__ float d_y2[NB*NFS*20*20];
__device__ float d_y3[NB*NFS*10*10];
__device__ float d_y4[NB*NFS*25];
__device__ float d_stats[4*48];
__device__ __align__(16) __half d_P[NB*NOBJ*HID];
__device__ __align__(16) __half d_Q[NB*NOBJ*HID];
__device__ __align__(16) __half d_R[NB*HID];
__device__ float d_xg[NB*HID];
__device__ float d_Wt[2*HID*HID];
__device__ __align__(16) __half d_Wh[3*HID*HID];
__device__ float d_g1t[63*HID];

// ------------------------------ helpers --------------------------------------
__device__ __forceinline__ uint32_t smem_u32(const void* p) {
    uint32_t a;
    asm("{ .reg .u64 t; cvta.to.shared.u64 t, %1; cvt.u32.u64 %0, t; }" : "=r"(a) : "l"(p));
    return a;
}
__device__ __forceinline__ void ldsm_x4(uint32_t* r, uint32_t addr) {
    asm volatile("ldmatrix.sync.aligned.m8n8.x4.shared.b16 {%0,%1,%2,%3}, [%4];"
                 : "=r"(r[0]), "=r"(r[1]), "=r"(r[2]), "=r"(r[3]) : "r"(addr));
}
__device__ __forceinline__ void mma16816(float* c, const uint32_t* a, uint32_t b0, uint32_t b1) {
    asm volatile("mma.sync.aligned.m16n8k16.row.col.f32.f16.f16.f32 "
                 "{%0,%1,%2,%3}, {%4,%5,%6,%7}, {%8,%9}, {%0,%1,%2,%3};"
                 : "+f"(c[0]), "+f"(c[1]), "+f"(c[2]), "+f"(c[3])
                 : "r"(a[0]), "r"(a[1]), "r"(a[2]), "r"(a[3]), "r"(b0), "r"(b1));
}
__device__ __forceinline__ uint32_t h2relu3(uint32_t a, uint32_t b, uint32_t c) {
    __half2 z = __float2half2_rn(0.f);
    __half2 r = __hmax2(__hadd2(__hadd2(*(__half2*)&a, *(__half2*)&b), *(__half2*)&c), z);
    return *(uint32_t*)&r;
}
// derive input-BN scale/shift from accumulated stats (tid<24)
__device__ __forceinline__ void bn_derive(int tid, int layer, float inv_count,
                                          const float* gamma, const float* beta,
                                          float* sc, float* sh) {
    if (tid < NFS) {
        float mean = d_stats[layer*48 + tid] * inv_count;
        float var  = d_stats[layer*48 + 24 + tid] * inv_count - mean*mean;
        float s    = gamma[tid] * rsqrtf(var + 1e-5f);
        sc[tid] = s;
        sh[tid] = beta[tid] - mean * s;
    }
}

// -------------------- prep: transposes, fp16 weights, zeroing ----------------
__global__ void prep_kernel(const float* __restrict__ g2w, const float* __restrict__ g3w,
                            const float* __restrict__ g4w, const float* __restrict__ f1w,
                            const float* __restrict__ fc2w, const float* __restrict__ g1w) {
    int idx = blockIdx.x * 256 + threadIdx.x;   // grid covers 196608
    if (idx < 2*HID*HID) {
        int t = idx >> 16, r = idx & 65535, k = r >> 8, n = r & 255;
        d_Wt[idx] = (t == 0 ? f1w : fc2w)[n*HID + k];
        d_xg[idx & (NB*HID - 1)] = 0.f;   // 131072 == NB*HID
    }
    if (idx < 3*HID*HID) {
        const float* s = (idx < 65536) ? g2w : (idx < 131072) ? g3w : g4w;
        d_Wh[idx] = __float2half(s[idx & 65535]);
    }
    if (idx < 63*HID) {
        int c = idx >> 8, n = idx & 255;
        d_g1t[idx] = g1w[n*63 + c];
    }
    if (idx < 4*48) d_stats[idx] = 0.f;
}

// --------------------------- conv1: 3ch 80->40 -------------------------------
// grid (4, NB) block 256. Thread: 4 co x 10 cols x 1 row.
__global__ void __launch_bounds__(256)
conv1_kernel(const float* __restrict__ img, float* __restrict__ out,
             const float* __restrict__ w, const float* __restrict__ cb) {
    __shared__ float tile[3*41*44];
    __shared__ float ws[648];
    __shared__ float red1[24][40], red2[24][40];

    const int n   = blockIdx.y;
    const int bx  = blockIdx.x;
    const int oy0 = (bx >> 1) * 20, ox0 = (bx & 1) * 20;
    const int tid = threadIdx.x;

    for (int i = tid; i < 648; i += 256) ws[i] = w[i];
    const int iy0 = oy0*2 - 1, ix0 = ox0*2 - 1;
    for (int e = tid; e < 3*41*44; e += 256) {
        int ci = e / 1804, r2 = e - ci*1804;
        int ly = r2 / 44, lx = r2 - ly*44;
        int iy = iy0 + ly, ix = ix0 + lx;
        tile[e] = (iy >= 0 && iy < 80 && ix >= 0 && ix < 80)
                  ? img[((size_t)n*3 + ci)*6400 + iy*80 + ix] : 0.f;
    }
    __syncthreads();

    const bool act = tid < 240;
    const int co0  = (tid / 40) * 4;
    const int rem  = tid % 40;
    const int r    = rem >> 1, half = rem & 1;

    float acc[4][10];
    if (act) {
        #pragma unroll
        for (int q = 0; q < 4; q++) {
            const float bq = cb[co0 + q];
            #pragma unroll
            for (int c = 0; c < 10; c++) acc[q][c] = bq;
        }
        #pragma unroll
        for (int ci = 0; ci < 3; ci++) {
            const float* tb = tile + ci*1804;
            #pragma unroll
            for (int ky = 0; ky < 3; ky++) {
                const float* row = tb + (2*r + ky)*44 + half*20;
                float4 a0 = *(const float4*)(row);
                float4 a1 = *(const float4*)(row + 4);
                float4 a2 = *(const float4*)(row + 8);
                float4 a3 = *(const float4*)(row + 12);
                float4 a4 = *(const float4*)(row + 16);
                float4 a5 = *(const float4*)(row + 20);
                const float x[24] = {a0.x,a0.y,a0.z,a0.w, a1.x,a1.y,a1.z,a1.w,
                                     a2.x,a2.y,a2.z,a2.w, a3.x,a3.y,a3.z,a3.w,
                                     a4.x,a4.y,a4.z,a4.w, a5.x,a5.y,a5.z,a5.w};
                #pragma unroll
                for (int q = 0; q < 4; q++) {
                    const float* wr = ws + (co0 + q)*27 + ci*9 + ky*3;
                    const float w0 = wr[0], w1 = wr[1], w2 = wr[2];
                    #pragma unroll
                    for (int c = 0; c < 10; c++)
                        acc[q][c] = fmaf(x[2*c], w0, fmaf(x[2*c+1], w1,
                                     fmaf(x[2*c+2], w2, acc[q][c])));
                }
            }
        }
        const int oy = oy0 + r, ox = ox0 + half*10;
        #pragma unroll
        for (int q = 0; q < 4; q++) {
            float s1 = 0.f, s2 = 0.f;
            float* op = out + ((size_t)n*24 + co0 + q)*1600 + oy*40 + ox;
            #pragma unroll
            for (int c = 0; c < 5; c++) {
                float y0 = fmaxf(acc[q][2*c],   0.f);
                float y1 = fmaxf(acc[q][2*c+1], 0.f);
                *(float2*)(op + 2*c) = make_float2(y0, y1);
                s1 += y0 + y1; s2 += y0*y0 + y1*y1;
            }
            red1[co0 + q][rem] = s1;
            red2[co0 + q][rem] = s2;
        }
    }
    __syncthreads();
    if (tid < 48) {
        const int co = tid % 24, st = tid / 24;
        const float (*rd)[40] = st ? red2 : red1;
        float s = 0.f;
        #pragma unroll
        for (int i = 0; i < 40; i++) s += rd[co][i];
        atomicAdd(&d_stats[st*24 + co], s);
    }
}

// --------------------------- conv2: 24ch 40->20 ------------------------------
// grid (2, NB) block 256 (240 active). Thread: 2 co x 10 cols x 1 row.
#define C2_TILE 0
#define C2_WS   22176
#define C2_SC   27360
#define C2_SH   27384
#define C2_R1   27408
#define C2_R2   27888
#define C2_BYTES (28368*4)
__global__ void __launch_bounds__(256)
conv2_kernel(const float* __restrict__ in, float* __restrict__ out,
             const float* __restrict__ w, const float* __restrict__ cb,
             const float* __restrict__ gamma, const float* __restrict__ beta) {
    extern __shared__ float dsm[];
    float* tile = dsm + C2_TILE;
    float* ws   = dsm + C2_WS;
    float* sc   = dsm + C2_SC;
    float* sh   = dsm + C2_SH;
    float* rd1  = dsm + C2_R1;
    float* rd2  = dsm + C2_R2;

    const int n   = blockIdx.y;
    const int ty  = blockIdx.x;       // output rows ty*10..+10, cols 0..19
    const int tid = threadIdx.x;

    bn_derive(tid, 0, 1.f/(NB*1600.f), gamma, beta, sc, sh);
    for (int i = tid; i < 5184; i += 256) ws[i] = w[i];
    __syncthreads();

    const int iy0 = ty*20 - 1;
    for (int e = tid; e < 24*21*44; e += 256) {
        int ci = e / 924, r2 = e - ci*924;
        int ly = r2 / 44, lx = r2 - ly*44;
        int iy = iy0 + ly, ix = lx - 1;
        float v = 0.f;
        if (iy >= 0 && iy < 40 && ix >= 0 && ix < 40)
            v = fmaf(in[((size_t)n*24 + ci)*1600 + iy*40 + ix], sc[ci], sh[ci]);
        tile[e] = v;
    }
    __syncthreads();

    const bool act = tid < 240;
    const int co0  = (tid / 20) * 2;
    const int rem  = tid % 20;
    const int r    = rem >> 1, half = rem & 1;

    float acc[2][10];
    if (act) {
        #pragma unroll
        for (int q = 0; q < 2; q++) {
            const float bq = cb[co0 + q];
            #pragma unroll
            for (int c = 0; c < 10; c++) acc[q][c] = bq;
        }
        #pragma unroll 4
        for (int ci = 0; ci < 24; ci++) {
            const float* tb = tile + ci*924;
            #pragma unroll
            for (int ky = 0; ky < 3; ky++) {
                const float* row = tb + (2*r + ky)*44 + half*20;
                float4 a0 = *(const float4*)(row);
                float4 a1 = *(const float4*)(row + 4);
                float4 a2 = *(const float4*)(row + 8);
                float4 a3 = *(const float4*)(row + 12);
                float4 a4 = *(const float4*)(row + 16);
                float4 a5 = *(const float4*)(row + 20);
                const float x[24] = {a0.x,a0.y,a0.z,a0.w, a1.x,a1.y,a1.z,a1.w,
                                     a2.x,a2.y,a2.z,a2.w, a3.x,a3.y,a3.z,a3.w,
                                     a4.x,a4.y,a4.z,a4.w, a5.x,a5.y,a5.z,a5.w};
                #pragma unroll
                for (int q = 0; q < 2; q++) {
                    const float* wr = ws + (co0 + q)*216 + ci*9 + ky*3;
                    const float w0 = wr[0], w1 = wr[1], w2 = wr[2];
                    #pragma unroll
                    for (int c = 0; c < 10; c++)
                        acc[q][c] = fmaf(x[2*c], w0, fmaf(x[2*c+1], w1,
                                     fmaf(x[2*c+2], w2, acc[q][c])));
                }
            }
        }
        const int oy = ty*10 + r, ox = half*10;
        #pragma unroll
        for (int q = 0; q < 2; q++) {
            float s1 = 0.f, s2 = 0.f;
            float* op = out + ((size_t)n*24 + co0 + q)*400 + oy*20 + ox;
            #pragma unroll
            for (int c = 0; c < 5; c++) {
                float y0 = fmaxf(acc[q][2*c],   0.f);
                float y1 = fmaxf(acc[q][2*c+1], 0.f);
                *(float2*)(op + 2*c) = make_float2(y0, y1);
                s1 += y0 + y1; s2 += y0*y0 + y1*y1;
            }
            rd1[(co0 + q)*20 + rem] = s1;
            rd2[(co0 + q)*20 + rem] = s2;
        }
    }
    __syncthreads();
    if (tid < 48) {
        const int co = tid % 24, st = tid / 24;
        const float* rd = (st ? rd2 : rd1) + co*20;
        float s = 0.f;
        #pragma unroll
        for (int i = 0; i < 20; i++) s += rd[i];
        atomicAdd(&d_stats[48 + st*24 + co], s);
    }
}

// --------------------------- conv3: 24ch 20->10 ------------------------------
// grid (1, NB) block 128 (120 active). Thread: 2 co x 10 cols x 1 row.
#define C3_TILE 0
#define C3_WS   12096
#define C3_SC   17280
#define C3_SH   17304
#define C3_R1   17328
#define C3_R2   17568
#define C3_BYTES (17808*4)
__global__ void __launch_bounds__(128)
conv3_kernel(const float* __restrict__ in, float* __restrict__ out,
             const float* __restrict__ w, const float* __restrict__ cb,
             const float* __restrict__ gamma, const float* __restrict__ beta) {
    extern __shared__ float dsm[];
    float* tile = dsm + C3_TILE;
    float* ws   = dsm + C3_WS;
    float* sc   = dsm + C3_SC;
    float* sh   = dsm + C3_SH;
    float* rd1  = dsm + C3_R1;
    float* rd2  = dsm + C3_R2;

    const int n   = blockIdx.y;
    const int tid = threadIdx.x;

    bn_derive(tid, 1, 1.f/(NB*400.f), gamma, beta, sc, sh);
    for (int i = tid; i < 5184; i += 128) ws[i] = w[i];
    __syncthreads();

    for (int e = tid; e < 24*21*24; e += 128) {
        int ci = e / 504, r2 = e - ci*504;
        int ly = r2 / 24, lx = r2 - ly*24;
        int iy = ly - 1, ix = lx - 1;
        float v = 0.f;
        if (iy >= 0 && iy < 20 && ix >= 0 && ix < 20)
            v = fmaf(in[((size_t)n*24 + ci)*400 + iy*20 + ix], sc[ci], sh[ci]);
        tile[e] = v;
    }
    __syncthreads();

    const bool act = tid < 120;
    const int co0  = (tid / 10) * 2;
    const int r    = tid % 10;

    float acc[2][10];
    if (act) {
        #pragma unroll
        for (int q = 0; q < 2; q++) {
            const float bq = cb[co0 + q];
            #pragma unroll
            for (int c = 0; c < 10; c++) acc[q][c] = bq;
        }
        #pragma unroll 4
        for (int ci = 0; ci < 24; ci++) {
            const float* tb = tile + ci*504;
            #pragma unroll
            for (int ky = 0; ky < 3; ky++) {
                const float* row = tb + (2*r + ky)*24;
                float4 a0 = *(const float4*)(row);
                float4 a1 = *(const float4*)(row + 4);
                float4 a2 = *(const float4*)(row + 8);
                float4 a3 = *(const float4*)(row + 12);
                float4 a4 = *(const float4*)(row + 16);
                float4 a5 = *(const float4*)(row + 20);
                const float x[24] = {a0.x,a0.y,a0.z,a0.w, a1.x,a1.y,a1.z,a1.w,
                                     a2.x,a2.y,a2.z,a2.w, a3.x,a3.y,a3.z,a3.w,
                                     a4.x,a4.y,a4.z,a4.w, a5.x,a5.y,a5.z,a5.w};
                #pragma unroll
                for (int q = 0; q < 2; q++) {
                    const float* wr = ws + (co0 + q)*216 + ci*9 + ky*3;
                    const float w0 = wr[0], w1 = wr[1], w2 = wr[2];
                    #pragma unroll
                    for (int c = 0; c < 10; c++)
                        acc[q][c] = fmaf(x[2*c], w0, fmaf(x[2*c+1], w1,
                                     fmaf(x[2*c+2], w2, acc[q][c])));
                }
            }
        }
        #pragma unroll
        for (int q = 0; q < 2; q++) {
            float s1 = 0.f, s2 = 0.f;
            float* op = out + ((size_t)n*24 + co0 + q)*100 + r*10;
            #pragma unroll
            for (int c = 0; c < 5; c++) {
                float y0 = fmaxf(acc[q][2*c],   0.f);
                float y1 = fmaxf(acc[q][2*c+1], 0.f);
                *(float2*)(op + 2*c) = make_float2(y0, y1);
                s1 += y0 + y1; s2 += y0*y0 + y1*y1;
            }
            rd1[(co0 + q)*10 + r] = s1;
            rd2[(co0 + q)*10 + r] = s2;
        }
    }
    __syncthreads();
    if (tid < 48) {
        const int co = tid % 24, st = tid / 24;
        const float* rd = (st ? rd2 : rd1) + co*10;
        float s = 0.f;
        #pragma unroll
        for (int i = 0; i < 10; i++) s += rd[i];
        atomicAdd(&d_stats[2*48 + st*24 + co], s);
    }
}

// --------------------------- conv4: 24ch 10->5 -------------------------------
// grid (1, NB) block 128 (120 active). Thread: 1 co x 5 cols x 1 row.
#define C4_TILE 0
#define C4_WS   3168
#define C4_SC   8352
#define C4_SH   8376
#define C4_R1   8400
#define C4_R2   8520
#define C4_BYTES (8640*4)
__global__ void __launch_bounds__(128)
conv4_kernel(const float* __restrict__ in, float* __restrict__ out,
             const float* __restrict__ w, const float* __restrict__ cb,
             const float* __restrict__ gamma, const float* __restrict__ beta) {
    extern __shared__ float dsm[];
    float* tile = dsm + C4_TILE;
    float* ws   = dsm + C4_WS;
    float* sc   = dsm + C4_SC;
    float* sh   = dsm + C4_SH;
    float* rd1  = dsm + C4_R1;
    float* rd2  = dsm + C4_R2;

    const int n   = blockIdx.y;
    const int tid = threadIdx.x;

    bn_derive(tid, 2, 1.f/(NB*100.f), gamma, beta, sc, sh);
    for (int i = tid; i < 5184; i += 128) ws[i] = w[i];
    __syncthreads();

    for (int e = tid; e < 24*11*12; e += 128) {
        int ci = e / 132, r2 = e - ci*132;
        int ly = r2 / 12, lx = r2 - ly*12;
        int iy = ly - 1, ix = lx - 1;
        float v = 0.f;
        if (iy >= 0 && iy < 10 && ix >= 0 && ix < 10)
            v = fmaf(in[((size_t)n*24 + ci)*100 + iy*10 + ix], sc[ci], sh[ci]);
        tile[e] = v;
    }
    __syncthreads();

    const bool act = tid < 120;
    const int co = tid / 5;
    const int r  = tid % 5;

    float acc[5];
    if (act) {
        const float bq = cb[co];
        #pragma unroll
        for (int c = 0; c < 5; c++) acc[c] = bq;
        #pragma unroll 4
        for (int ci = 0; ci < 24; ci++) {
            const float* tb = tile + ci*132;
            #pragma unroll
            for (int ky = 0; ky < 3; ky++) {
                const float* row = tb + (2*r + ky)*12;
                float4 a0 = *(const float4*)(row);
                float4 a1 = *(const float4*)(row + 4);
                float4 a2 = *(const float4*)(row + 8);
                const float x[12] = {a0.x,a0.y,a0.z,a0.w, a1.x,a1.y,a1.z,a1.w,
                                     a2.x,a2.y,a2.z,a2.w};
                const float* wr = ws + co*216 + ci*9 + ky*3;
                const float w0 = wr[0], w1 = wr[1], w2 = wr[2];
                #pragma unroll
                for (int c = 0; c < 5; c++)
                    acc[c] = fmaf(x[2*c], w0, fmaf(x[2*c+1], w1,
                               fmaf(x[2*c+2], w2, acc[c])));
            }
        }
        float s1 = 0.f, s2 = 0.f;
        float* op = out + ((size_t)n*24 + co)*25 + r*5;
        #pragma unroll
        for (int c = 0; c < 5; c++) {
            float y = fmaxf(acc[c], 0.f);
            op[c] = y;
            s1 += y; s2 += y*y;
        }
        rd1[co*5 + r] = s1;
        rd2[co*5 + r] = s2;
    }
    __syncthreads();
    if (tid < 48) {
        const int co2 = tid % 24, st = tid / 24;
        const float* rd = (st ? rd2 : rd1) + co2*5;
        float s = 0.f;
        #pragma unroll
        for (int i = 0; i < 5; i++) s += rd[i];
        atomicAdd(&d_stats[3*48 + st*24 + co2], s);
    }
}

// -------------------- proj: per-batch, register weights ----------------------
__global__ void __launch_bounds__(256)
proj_kernel(const float* __restrict__ qst, const float* __restrict__ g1b,
            const float* __restrict__ bg4, const float* __restrict__ bb4) {
    __shared__ float sc[24], sh[24];
    __shared__ float feat[NOBJ][26];
    __shared__ float qv[11];
    const int b   = blockIdx.x;
    const int tid = threadIdx.x;

    bn_derive(tid, 3, 1.f/(NB*25.f), bg4, bb4, sc, sh);
    if (tid >= 32 && tid < 43) qv[tid - 32] = qst[(tid - 32)*NB + b];
    __syncthreads();

    for (int e = tid; e < NOBJ*24; e += 256) {
        int o = e / 24, c = e - o*24;
        feat[o][c] = fmaf(d_y4[((size_t)b*24 + c)*25 + o], sc[c], sh[c]);
    }
    if (tid < 2*NOBJ) {
        int o = tid >> 1;
        if (tid & 1) feat[o][25] = ((float)(o % 5) - 2.f) * 0.5f;
        else         feat[o][24] = ((float)(o / 5) - 2.f) * 0.5f;
    }

    const int n = tid;
    float wp[26], wq[26];
    #pragma unroll
    for (int c = 0; c < 26; c++) {
        wp[c] = d_g1t[c*HID + n];
        wq[c] = d_g1t[(26 + c)*HID + n];
    }
    float rr = g1b[n];
    #pragma unroll
    for (int c = 0; c < 11; c++) rr = fmaf(d_g1t[(52 + c)*HID + n], qv[c], rr);
    __syncthreads();
    d_R[(size_t)b*HID + n] = __float2half(rr);

    #pragma unroll 1
    for (int o = 0; o < NOBJ; o++) {
        float p = 0.f, q = 0.f;
        #pragma unroll
        for (int c = 0; c < 26; c++) {
            const float f = feat[o][c];
            p = fmaf(wp[c], f, p);
            q = fmaf(wq[c], f, q);
        }
        d_P[((size_t)b*NOBJ + o)*HID + n] = __float2half(p);
        d_Q[((size_t)b*NOBJ + o)*HID + n] = __float2half(q);
    }
}

// ------------------ fp16 mma g2/g3/g4 fused MLP (unchanged) ------------------
__device__ __forceinline__ void load_W_async(uint32_t sb, const __half* W, int tid) {
    #pragma unroll 8
    for (int it = 0; it < 32; it++) {
        int idx = it*256 + tid;
        int n = idx >> 5;
        int c = idx & 31;
        uint32_t dst = sb + SM_W + n*LDAB + c*16;
        size_t src = __cvta_generic_to_global((const char*)(W + n*HID) + c*16);
        asm volatile("cp.async.cg.shared.global [%0], [%1], 16;\n" :: "r"(dst), "l"(src));
    }
    asm volatile("cp.async.commit_group;\n" ::: "memory");
}

__global__ void __launch_bounds__(256, 1)
gmlp_mma_kernel(const float* __restrict__ g2b, const float* __restrict__ g3b,
                const float* __restrict__ g4b) {
    extern __shared__ char smem[];
    const uint32_t sb = smem_u32(smem);
    float* bias_s = (float*)smem;

    const int tid  = threadIdx.x;
    const int wid  = tid >> 5;
    const int lane = tid & 31;
    const int blk  = blockIdx.x;
    const int b    = blk / GTILES;
    const int t    = blk - b*GTILES;
    const int row0 = t * 128;
    const int valid = (NPAIR - row0 < 128) ? (NPAIR - row0) : 128;

    load_W_async(sb, d_Wh, tid);

    bias_s[tid]       = g2b[tid];
    bias_s[256 + tid] = g3b[tid];
    bias_s[512 + tid] = g4b[tid];
    if (tid < 128) {
        bias_s[128 + tid]       = g2b[128 + tid];
        bias_s[256 + 128 + tid] = g3b[128 + tid];
        bias_s[512 + 128 + tid] = g4b[128 + tid];
    }

    const __half* Ph = d_P + (size_t)b*NOBJ*HID;
    const __half* Qh = d_Q + (size_t)b*NOBJ*HID;
    const __half* Rh = d_R + (size_t)b*HID;
    #pragma unroll 4
    for (int it = 0; it < 16; it++) {
        int v = it*256 + tid;
        int m = v >> 5;
        int u = v & 31;
        int k0 = u * 8;
        uint4 o = {0u, 0u, 0u, 0u};
        if (m < valid) {
            int p = row0 + m;
            int j = p / NOBJ;
            int i = p - j*NOBJ;
            uint4 P4 = *(const uint4*)(Ph + i*HID + k0);
            uint4 Q4 = *(const uint4*)(Qh + j*HID + k0);
            uint4 R4 = *(const uint4*)(Rh + k0);
            o.x = h2relu3(P4.x, Q4.x, R4.x);
            o.y = h2relu3(P4.y, Q4.y, R4.y);
            o.z = h2relu3(P4.z, Q4.z, R4.z);
            o.w = h2relu3(P4.w, Q4.w, R4.w);
        }
        uint32_t addr = sb + SM_H + m*LDAB + u*16;
        asm volatile("st.shared.v4.b32 [%0], {%1,%2,%3,%4};" :: "r"(addr),
                     "r"(o.x), "r"(o.y), "r"(o.z), "r"(o.w));
    }
    asm volatile("cp.async.wait_group 0;\n" ::: "memory");
    __syncthreads();

    const int m0 = (wid & 1) * 64;
    const int n0 = (wid >> 1) * 64;
    const uint32_t aAddr0 = sb + SM_H + (m0 + (lane & 15))*LDAB + (8*(lane >> 4))*2;
    const uint32_t bAddr0 = sb + SM_W + (n0 + (lane & 7) + (lane >> 4)*8)*LDAB
                                       + (((lane >> 3) & 1)*8)*2;

    for (int L = 0; L < 3; L++) {
        float acc[4][8][4];
        #pragma unroll
        for (int mi = 0; mi < 4; mi++)
            #pragma unroll
            for (int nj = 0; nj < 8; nj++)
                #pragma unroll
                for (int e = 0; e < 4; e++) acc[mi][nj][e] = 0.f;

        #pragma unroll 1
        for (int ks = 0; ks < 16; ks++) {
            const uint32_t koff = ks * 32;
            uint32_t a[4][4], bfr[4][4];
            #pragma unroll
            for (int mi = 0; mi < 4; mi++)
                ldsm_x4(a[mi], aAddr0 + mi*16*LDAB + koff);
            #pragma unroll
            for (int nt = 0; nt < 4; nt++)
                ldsm_x4(bfr[nt], bAddr0 + nt*16*LDAB + koff);
            #pragma unroll
            for (int mi = 0; mi < 4; mi++)
                #pragma unroll
                for (int nt = 0; nt < 4; nt++) {
                    mma16816(acc[mi][nt*2],     a[mi], bfr[nt][0], bfr[nt][1]);
                    mma16816(acc[mi][nt*2 + 1], a[mi], bfr[nt][2], bfr[nt][3]);
                }
        }
        __syncthreads();

        if (L < 2) {
            load_W_async(sb, d_Wh + (size_t)(L+1)*HID*HID, tid);
            const float* bl = bias_s + L*256;
            #pragma unroll
            for (int mi = 0; mi < 4; mi++) {
                const int r0 = m0 + mi*16 + lane/4;
                #pragma unroll
                for (int nj = 0; nj < 8; nj++) {
                    const int c0 = n0 + nj*8 + (lane & 3)*2;
                    __half2 q0 = __floats2half2_rn(
                        fmaxf(acc[mi][nj][0] + bl[c0],     0.f),
                        fmaxf(acc[mi][nj][1] + bl[c0 + 1], 0.f));
                    __half2 q1 = __floats2half2_rn(
                        fmaxf(acc[mi][nj][2] + bl[c0],     0.f),
                        fmaxf(acc[mi][nj][3] + bl[c0 + 1], 0.f));
                    *(uint32_t*)(smem + SM_H + r0*LDAB + c0*2)       = *(uint32_t*)&q0;
                    *(uint32_t*)(smem + SM_H + (r0 + 8)*LDAB + c0*2) = *(uint32_t*)&q1;
                }
            }
            asm volatile("cp.async.wait_group 0;\n" ::: "memory");
            __syncthreads();
        } else {
            const float* bl = bias_s + 512;
            #pragma unroll
            for (int nj = 0; nj < 8; nj++) {
                const int c0 = n0 + nj*8 + (lane & 3)*2;
                float v0 = 0.f, v1 = 0.f;
                #pragma unroll
                for (int mi = 0; mi < 4; mi++) {
                    const int ra = m0 + mi*16 + lane/4;
                    if (ra < valid) {
                        v0 += fmaxf(acc[mi][nj][0] + bl[c0],     0.f);
                        v1 += fmaxf(acc[mi][nj][1] + bl[c0 + 1], 0.f);
                    }
                    if (ra + 8 < valid) {
                        v0 += fmaxf(acc[mi][nj][2] + bl[c0],     0.f);
                        v1 += fmaxf(acc[mi][nj][3] + bl[c0 + 1], 0.f);
                    }
                }
                #pragma unroll
                for (int off = 4; off < 32; off <<= 1) {
                    v0 += __shfl_xor_sync(0xffffffffu, v0, off);
                    v1 += __shfl_xor_sync(0xffffffffu, v1, off);
                }
                if (lane < 4) {
                    atomicAdd(&d_xg[(size_t)b*HID + c0],     v0);
                    atomicAdd(&d_xg[(size_t)b*HID + c0 + 1], v1);
                }
            }
        }
    }
}

// ------------------------------- head (8 batches/block) ----------------------
__global__ void __launch_bounds__(256)
head_kernel(const float* __restrict__ f1b, const float* __restrict__ fc2b,
            const float* __restrict__ fc3w, const float* __restrict__ fc3b,
            float* __restrict__ out) {
    __shared__ float xa[8][HID], xb[8][HID];
    __shared__ float lg[8][10];
    const int b0 = blockIdx.x * 8;
    const int n  = threadIdx.x;
    const float* f1wt  = d_Wt;
    const float* fc2wt = d_Wt + HID*HID;

    #pragma unroll
    for (int bi = 0; bi < 8; bi++) xa[bi][n] = d_xg[(size_t)(b0 + bi)*HID + n];
    __syncthreads();

    {
        float a[8];
        const float bb = f1b[n];
        #pragma unroll
        for (int bi = 0; bi < 8; bi++) a[bi] = bb;
        for (int k = 0; k < HID; k++) {
            const float w = f1wt[k*HID + n];
            #pragma unroll
            for (int bi = 0; bi < 8; bi++) a[bi] = fmaf(w, xa[bi][k], a[bi]);
        }
        #pragma unroll
        for (int bi = 0; bi < 8; bi++) xb[bi][n] = fmaxf(a[bi], 0.f);
    }
    __syncthreads();
    {
        float a[8];
        const float bb = fc2b[n];
        #pragma unroll
        for (int bi = 0; bi < 8; bi++) a[bi] = bb;
        for (int k = 0; k < HID; k++) {
            const float w = fc2wt[k*HID + n];
            #pragma unroll
            for (int bi = 0; bi < 8; bi++) a[bi] = fmaf(w, xb[bi][k], a[bi]);
        }
        #pragma unroll
        for (int bi = 0; bi < 8; bi++) xa[bi][n] = fmaxf(a[bi], 0.f);
    }
    __syncthreads();

    if (n < 80) {
        const int co = n % 10, bi = n / 10;
        float l = fc3b[co];
        const float* wr = fc3w + co*HID;
        for (int k = 0; k < HID; k++) l = fmaf(wr[k], xa[bi][k], l);
        lg[bi][co] = l;
    }
    __syncthreads();
    if (n < 8) {
        float mx = lg[n][0];
        #pragma unroll
        for (int c = 1; c < 10; c++) mx = fmaxf(mx, lg[n][c]);
        float se = 0.f;
        #pragma unroll
        for (int c = 0; c < 10; c++) se += expf(lg[n][c] - mx);
        const float lse = mx + logf(se);
        #pragma unroll
        for (int c = 0; c < 10; c++) out[(b0 + n)*10 + c] = lg[n][c] - lse;
    }
}

// ----------------------------- launcher --------------------------------------
extern "C" void kernel_launch(void* const* d_in, const int* in_sizes, int n_in,
                              void* d_out, int out_size) {
    const float* img  = (const float*)d_in[0];
    const float* qst  = (const float*)d_in[1];
    const float* cw1  = (const float*)d_in[2];
    const float* cb1  = (const float*)d_in[3];
    const float* bg1  = (const float*)d_in[4];
    const float* bb1  = (const float*)d_in[5];
    const float* cw2  = (const float*)d_in[6];
    const float* cb2  = (const float*)d_in[7];
    const float* bg2  = (const float*)d_in[8];
    const float* bb2  = (const float*)d_in[9];
    const float* cw3  = (const float*)d_in[10];
    const float* cb3  = (const float*)d_in[11];
    const float* bg3  = (const float*)d_in[12];
    const float* bb3  = (const float*)d_in[13];
    const float* cw4  = (const float*)d_in[14];
    const float* cb4  = (const float*)d_in[15];
    const float* bg4  = (const float*)d_in[16];
    const float* bb4  = (const float*)d_in[17];
    const float* g1w  = (const float*)d_in[18];
    const float* g1b  = (const float*)d_in[19];
    const float* g2w  = (const float*)d_in[20];
    const float* g2b  = (const float*)d_in[21];
    const float* g3w  = (const float*)d_in[22];
    const float* g3b  = (const float*)d_in[23];
    const float* g4w  = (const float*)d_in[24];
    const float* g4b  = (const float*)d_in[25];
    const float* f1w  = (const float*)d_in[26];
    const float* f1b  = (const float*)d_in[27];
    const float* fc2w = (const float*)d_in[28];
    const float* fc2b = (const float*)d_in[29];
    const float* fc3w = (const float*)d_in[30];
    const float* fc3b = (const float*)d_in[31];
    float* out = (float*)d_out;

    float *y1, *y2, *y3, *y4;
    cudaGetSymbolAddress((void**)&y1, d_y1);
    cudaGetSymbolAddress((void**)&y2, d_y2);
    cudaGetSymbolAddress((void**)&y3, d_y3);
    cudaGetSymbolAddress((void**)&y4, d_y4);

    cudaFuncSetAttribute(gmlp_mma_kernel, cudaFuncAttributeMaxDynamicSharedMemorySize, SM_TOTAL);
    cudaFuncSetAttribute(conv2_kernel, cudaFuncAttributeMaxDynamicSharedMemorySize, C2_BYTES);
    cudaFuncSetAttribute(conv3_kernel, cudaFuncAttributeMaxDynamicSharedMemorySize, C3_BYTES);
    cudaFuncSetAttribute(conv4_kernel, cudaFuncAttributeMaxDynamicSharedMemorySize, C4_BYTES);

    prep_kernel<<<768, 256>>>(g2w, g3w, g4w, f1w, fc2w, g1w);

    conv1_kernel<<<dim3(4, NB), 256>>>(img, y1, cw1, cb1);
    conv2_kernel<<<dim3(2, NB), 256, C2_BYTES>>>(y1, y2, cw2, cb2, bg1, bb1);
    conv3_kernel<<<dim3(1, NB), 128, C3_BYTES>>>(y2, y3, cw3, cb3, bg2, bb2);
    conv4_kernel<<<dim3(1, NB), 128, C4_BYTES>>>(y3, y4, cw4, cb4, bg3, bb3);

    proj_kernel<<<NB, 256>>>(qst, g1b, bg4, bb4);

    gmlp_mma_kernel<<<NB*GTILES, 256, SM_TOTAL>>>(g2b, g3b, g4b);

    head_kernel<<<NB/8, 256>>>(f1b, fc2b, fc3w, fc3b, out);
}

// round 9
// speedup vs baseline: 6.5720x; 1.0325x over previous
#include <cuda_runtime.h>
#include <cuda_fp16.h>
#include <math.h>
#include <stdint.h>

// ---------------------------------------------------------------------------
// RelNet forward.
//   convs: register-blocked tiled direct conv, spill-free microtiles
//          (co-blocked: 2-4 output channels x 5 cols per thread), float2
//          window staging, pitch-26 tiles; BN folded into consumer.
//   g1:    per-batch proj, weights register-resident, P/Q/R fp16.
//   g2-g4: fp16 mma.sync m16n8k16 fused 3-layer chain (verified).
//   head:  8 batches per block.
// ---------------------------------------------------------------------------

#define NB     512
#define NFS    24
#define HID    256
#define NOBJ   25
#define NPAIR  625
#define GTILES 5

#define LDAB   528
#define SM_H    3072
#define SM_W    70656
#define SM_TOTAL 205824

// ------------------------- device scratch (static) ---------------------------
__device__ float d_y1[NB*NFS*40*40];
__device__ float d_y2[NB*NFS*20*20];
__device__ float d_y3[NB*NFS*10*10];
__device__ float d_y4[NB*NFS*25];
__device__ float d_stats[4*48];
__device__ __align__(16) __half d_P[NB*NOBJ*HID];
__device__ __align__(16) __half d_Q[NB*NOBJ*HID];
__device__ __align__(16) __half d_R[NB*HID];
__device__ float d_xg[NB*HID];
__device__ float d_Wt[2*HID*HID];
__device__ __align__(16) __half d_Wh[3*HID*HID];
__device__ float d_g1t[63*HID];

// ------------------------------ helpers --------------------------------------
__device__ __forceinline__ uint32_t smem_u32(const void* p) {
    uint32_t a;
    asm("{ .reg .u64 t; cvta.to.shared.u64 t, %1; cvt.u32.u64 %0, t; }" : "=r"(a) : "l"(p));
    return a;
}
__device__ __forceinline__ void ldsm_x4(uint32_t* r, uint32_t addr) {
    asm volatile("ldmatrix.sync.aligned.m8n8.x4.shared.b16 {%0,%1,%2,%3}, [%4];"
                 : "=r"(r[0]), "=r"(r[1]), "=r"(r[2]), "=r"(r[3]) : "r"(addr));
}
__device__ __forceinline__ void mma16816(float* c, const uint32_t* a, uint32_t b0, uint32_t b1) {
    asm volatile("mma.sync.aligned.m16n8k16.row.col.f32.f16.f16.f32 "
                 "{%0,%1,%2,%3}, {%4,%5,%6,%7}, {%8,%9}, {%0,%1,%2,%3};"
                 : "+f"(c[0]), "+f"(c[1]), "+f"(c[2]), "+f"(c[3])
                 : "r"(a[0]), "r"(a[1]), "r"(a[2]), "r"(a[3]), "r"(b0), "r"(b1));
}
__device__ __forceinline__ uint32_t h2relu3(uint32_t a, uint32_t b, uint32_t c) {
    __half2 z = __float2half2_rn(0.f);
    __half2 r = __hmax2(__hadd2(__hadd2(*(__half2*)&a, *(__half2*)&b), *(__half2*)&c), z);
    return *(uint32_t*)&r;
}
__device__ __forceinline__ void bn_derive(int tid, int layer, float inv_count,
                                          const float* gamma, const float* beta,
                                          float* sc, float* sh) {
    if (tid < NFS) {
        float mean = d_stats[layer*48 + tid] * inv_count;
        float var  = d_stats[layer*48 + 24 + tid] * inv_count - mean*mean;
        float s    = gamma[tid] * rsqrtf(var + 1e-5f);
        sc[tid] = s;
        sh[tid] = beta[tid] - mean * s;
    }
}

// -------------------- prep: transposes, fp16 weights, zeroing ----------------
__global__ void prep_kernel(const float* __restrict__ g2w, const float* __restrict__ g3w,
                            const float* __restrict__ g4w, const float* __restrict__ f1w,
                            const float* __restrict__ fc2w, const float* __restrict__ g1w) {
    int idx = blockIdx.x * 256 + threadIdx.x;
    if (idx < 2*HID*HID) {
        int t = idx >> 16, r = idx & 65535, k = r >> 8, n = r & 255;
        d_Wt[idx] = (t == 0 ? f1w : fc2w)[n*HID + k];
        d_xg[idx & (NB*HID - 1)] = 0.f;
    }
    if (idx < 3*HID*HID) {
        const float* s = (idx < 65536) ? g2w : (idx < 131072) ? g3w : g4w;
        d_Wh[idx] = __float2half(s[idx & 65535]);
    }
    if (idx < 63*HID) {
        int c = idx >> 8, n = idx & 255;
        d_g1t[idx] = g1w[n*63 + c];
    }
    if (idx < 4*48) d_stats[idx] = 0.f;
}

// --------------------------- conv1: 3ch 80->40 -------------------------------
// grid (16, NB) block 256 (240 active). Thread: 2 co x 5 cols x 1 row.
__global__ void __launch_bounds__(256)
conv1_kernel(const float* __restrict__ img, float* __restrict__ out,
             const float* __restrict__ w, const float* __restrict__ cb) {
    __shared__ float tile[3*21*26];
    __shared__ float ws[648];
    __shared__ float red1[24][20], red2[24][20];

    const int n   = blockIdx.y;
    const int bx  = blockIdx.x;               // 0..15 -> 4x4 tiles of 10x10
    const int ty  = bx >> 2, tx = bx & 3;
    const int tid = threadIdx.x;

    for (int i = tid; i < 648; i += 256) ws[i] = w[i];
    const int iy0 = ty*20 - 1, ix0 = tx*20 - 1;
    for (int e = tid; e < 3*21*26; e += 256) {
        int ci = e / 546, r2 = e - ci*546;
        int ly = r2 / 26, lx = r2 - ly*26;
        int iy = iy0 + ly, ix = ix0 + lx;
        tile[e] = (lx < 21 && iy >= 0 && iy < 80 && ix >= 0 && ix < 80)
                  ? img[((size_t)n*3 + ci)*6400 + iy*80 + ix] : 0.f;
    }
    __syncthreads();

    if (tid < 240) {
        const int co0  = (tid / 20) * 2;      // 12 co-pairs
        const int rem  = tid % 20;
        const int r    = rem >> 1, half = rem & 1;

        float acc[2][5];
        #pragma unroll
        for (int q = 0; q < 2; q++) {
            const float bq = cb[co0 + q];
            #pragma unroll
            for (int c = 0; c < 5; c++) acc[q][c] = bq;
        }
        #pragma unroll
        for (int ci = 0; ci < 3; ci++) {
            const float* tb = tile + ci*546;
            #pragma unroll
            for (int ky = 0; ky < 3; ky++) {
                const float2* row = (const float2*)(tb + (2*r + ky)*26 + half*10);
                float x[12];
                #pragma unroll
                for (int t = 0; t < 6; t++) {
                    float2 v = row[t];
                    x[2*t] = v.x; x[2*t+1] = v.y;
                }
                #pragma unroll
                for (int q = 0; q < 2; q++) {
                    const float* wr = ws + (co0 + q)*27 + ci*9 + ky*3;
                    const float w0 = wr[0], w1 = wr[1], w2 = wr[2];
                    #pragma unroll
                    for (int c = 0; c < 5; c++)
                        acc[q][c] = fmaf(x[2*c], w0, fmaf(x[2*c+1], w1,
                                     fmaf(x[2*c+2], w2, acc[q][c])));
                }
            }
        }
        const int oy = ty*10 + r, ox = tx*10 + half*5;
        #pragma unroll
        for (int q = 0; q < 2; q++) {
            float s1 = 0.f, s2 = 0.f;
            float* op = out + ((size_t)n*24 + co0 + q)*1600 + oy*40 + ox;
            #pragma unroll
            for (int c = 0; c < 5; c++) {
                float y = fmaxf(acc[q][c], 0.f);
                op[c] = y;
                s1 += y; s2 += y*y;
            }
            red1[co0 + q][rem] = s1;
            red2[co0 + q][rem] = s2;
        }
    }
    __syncthreads();
    if (tid < 48) {
        const int co = tid % 24, st = tid / 24;
        const float (*rd)[20] = st ? red2 : red1;
        float s = 0.f;
        #pragma unroll
        for (int i = 0; i < 20; i++) s += rd[co][i];
        atomicAdd(&d_stats[st*24 + co], s);
    }
}

// --------------------- conv2: 24ch 40->20, 4 tiles of 10x10 ------------------
// block 128 (120 active). Thread: 4 co x 5 cols x 1 row.
#define C2_TILE 0                    // 24*21*26 = 13104
#define C2_WS   13104                // 5184
#define C2_SC   18288
#define C2_SH   18312
#define C2_R1   18336                // 24*20
#define C2_R2   18816
#define C2_BYTES (19296*4)
__global__ void __launch_bounds__(128)
conv2_kernel(const float* __restrict__ in, float* __restrict__ out,
             const float* __restrict__ w, const float* __restrict__ cb,
             const float* __restrict__ gamma, const float* __restrict__ beta) {
    extern __shared__ float dsm[];
    float* tile = dsm + C2_TILE;
    float* ws   = dsm + C2_WS;
    float* sc   = dsm + C2_SC;
    float* sh   = dsm + C2_SH;
    float* rd1  = dsm + C2_R1;
    float* rd2  = dsm + C2_R2;

    const int n   = blockIdx.y;
    const int bx  = blockIdx.x;               // 0..3 -> 2x2 tiles of 10x10
    const int ty  = bx >> 1, tx = bx & 1;
    const int tid = threadIdx.x;

    bn_derive(tid, 0, 1.f/(NB*1600.f), gamma, beta, sc, sh);
    for (int i = tid; i < 5184; i += 128) ws[i] = w[i];
    __syncthreads();

    const int iy0 = ty*20 - 1, ix0 = tx*20 - 1;
    for (int e = tid; e < 24*546; e += 128) {
        int ci = e / 546, r2 = e - ci*546;
        int ly = r2 / 26, lx = r2 - ly*26;
        int iy = iy0 + ly, ix = ix0 + lx;
        float v = 0.f;
        if (lx < 21 && iy >= 0 && iy < 40 && ix >= 0 && ix < 40)
            v = fmaf(in[((size_t)n*24 + ci)*1600 + iy*40 + ix], sc[ci], sh[ci]);
        tile[e] = v;
    }
    __syncthreads();

    if (tid < 120) {
        const int co0 = (tid / 20) * 4;       // 6 co-quads
        const int rem = tid % 20;
        const int r   = rem >> 1, half = rem & 1;

        float acc[4][5];
        #pragma unroll
        for (int q = 0; q < 4; q++) {
            const float bq = cb[co0 + q];
            #pragma unroll
            for (int c = 0; c < 5; c++) acc[q][c] = bq;
        }
        #pragma unroll 2
        for (int ci = 0; ci < 24; ci++) {
            const float* tb = tile + ci*546;
            #pragma unroll
            for (int ky = 0; ky < 3; ky++) {
                const float2* row = (const float2*)(tb + (2*r + ky)*26 + half*10);
                float x[12];
                #pragma unroll
                for (int t = 0; t < 6; t++) {
                    float2 v = row[t];
                    x[2*t] = v.x; x[2*t+1] = v.y;
                }
                #pragma unroll
                for (int q = 0; q < 4; q++) {
                    const float* wr = ws + (co0 + q)*216 + ci*9 + ky*3;
                    const float w0 = wr[0], w1 = wr[1], w2 = wr[2];
                    #pragma unroll
                    for (int c = 0; c < 5; c++)
                        acc[q][c] = fmaf(x[2*c], w0, fmaf(x[2*c+1], w1,
                                     fmaf(x[2*c+2], w2, acc[q][c])));
                }
            }
        }
        const int oy = ty*10 + r, ox = tx*10 + half*5;
        #pragma unroll
        for (int q = 0; q < 4; q++) {
            float s1 = 0.f, s2 = 0.f;
            float* op = out + ((size_t)n*24 + co0 + q)*400 + oy*20 + ox;
            #pragma unroll
            for (int c = 0; c < 5; c++) {
                float y = fmaxf(acc[q][c], 0.f);
                op[c] = y;
                s1 += y; s2 += y*y;
            }
            rd1[(co0 + q)*20 + rem] = s1;
            rd2[(co0 + q)*20 + rem] = s2;
        }
    }
    __syncthreads();
    if (tid < 48) {
        const int co = tid % 24, st = tid / 24;
        const float* rd = (st ? rd2 : rd1) + co*20;
        float s = 0.f;
        #pragma unroll
        for (int i = 0; i < 20; i++) s += rd[i];
        atomicAdd(&d_stats[48 + st*24 + co], s);
    }
}

// --------------------------- conv3: 24ch 20->10 ------------------------------
// grid (1, NB) block 128 (120 active). Thread: 4 co x 5 cols x 1 row.
__global__ void __launch_bounds__(128)
conv3_kernel(const float* __restrict__ in, float* __restrict__ out,
             const float* __restrict__ w, const float* __restrict__ cb,
             const float* __restrict__ gamma, const float* __restrict__ beta) {
    extern __shared__ float dsm[];
    float* tile = dsm + C2_TILE;
    float* ws   = dsm + C2_WS;
    float* sc   = dsm + C2_SC;
    float* sh   = dsm + C2_SH;
    float* rd1  = dsm + C2_R1;
    float* rd2  = dsm + C2_R2;

    const int n   = blockIdx.y;
    const int tid = threadIdx.x;

    bn_derive(tid, 1, 1.f/(NB*400.f), gamma, beta, sc, sh);
    for (int i = tid; i < 5184; i += 128) ws[i] = w[i];
    __syncthreads();

    for (int e = tid; e < 24*546; e += 128) {
        int ci = e / 546, r2 = e - ci*546;
        int ly = r2 / 26, lx = r2 - ly*26;
        int iy = ly - 1, ix = lx - 1;
        float v = 0.f;
        if (lx < 21 && iy >= 0 && iy < 20 && ix >= 0 && ix < 20)
            v = fmaf(in[((size_t)n*24 + ci)*400 + iy*20 + ix], sc[ci], sh[ci]);
        tile[e] = v;
    }
    __syncthreads();

    if (tid < 120) {
        const int co0 = (tid / 20) * 4;
        const int rem = tid % 20;
        const int r   = rem >> 1, half = rem & 1;

        float acc[4][5];
        #pragma unroll
        for (int q = 0; q < 4; q++) {
            const float bq = cb[co0 + q];
            #pragma unroll
            for (int c = 0; c < 5; c++) acc[q][c] = bq;
        }
        #pragma unroll 2
        for (int ci = 0; ci < 24; ci++) {
            const float* tb = tile + ci*546;
            #pragma unroll
            for (int ky = 0; ky < 3; ky++) {
                const float2* row = (const float2*)(tb + (2*r + ky)*26 + half*10);
                float x[12];
                #pragma unroll
                for (int t = 0; t < 6; t++) {
                    float2 v = row[t];
                    x[2*t] = v.x; x[2*t+1] = v.y;
                }
                #pragma unroll
                for (int q = 0; q < 4; q++) {
                    const float* wr = ws + (co0 + q)*216 + ci*9 + ky*3;
                    const float w0 = wr[0], w1 = wr[1], w2 = wr[2];
                    #pragma unroll
                    for (int c = 0; c < 5; c++)
                        acc[q][c] = fmaf(x[2*c], w0, fmaf(x[2*c+1], w1,
                                     fmaf(x[2*c+2], w2, acc[q][c])));
                }
            }
        }
        #pragma unroll
        for (int q = 0; q < 4; q++) {
            float s1 = 0.f, s2 = 0.f;
            float* op = out + ((size_t)n*24 + co0 + q)*100 + r*10 + half*5;
            #pragma unroll
            for (int c = 0; c < 5; c++) {
                float y = fmaxf(acc[q][c], 0.f);
                op[c] = y;
                s1 += y; s2 += y*y;
            }
            rd1[(co0 + q)*20 + rem] = s1;
            rd2[(co0 + q)*20 + rem] = s2;
        }
    }
    __syncthreads();
    if (tid < 48) {
        const int co = tid % 24, st = tid / 24;
        const float* rd = (st ? rd2 : rd1) + co*20;
        float s = 0.f;
        #pragma unroll
        for (int i = 0; i < 20; i++) s += rd[i];
        atomicAdd(&d_stats[2*48 + st*24 + co], s);
    }
}

// --------------------------- conv4: 24ch 10->5 -------------------------------
// grid (1, NB) block 128 (120 active). Thread: 1 co x 5 cols x 1 row.
#define C4_TILE 0                    // 24*11*14 = 3696
#define C4_WS   3696
#define C4_SC   8880
#define C4_SH   8904
#define C4_R1   8928                 // 24*5
#define C4_R2   9048
#define C4_BYTES (9168*4)
__global__ void __launch_bounds__(128)
conv4_kernel(const float* __restrict__ in, float* __restrict__ out,
             const float* __restrict__ w, const float* __restrict__ cb,
             const float* __restrict__ gamma, const float* __restrict__ beta) {
    extern __shared__ float dsm[];
    float* tile = dsm + C4_TILE;
    float* ws   = dsm + C4_WS;
    float* sc   = dsm + C4_SC;
    float* sh   = dsm + C4_SH;
    float* rd1  = dsm + C4_R1;
    float* rd2  = dsm + C4_R2;

    const int n   = blockIdx.y;
    const int tid = threadIdx.x;

    bn_derive(tid, 2, 1.f/(NB*100.f), gamma, beta, sc, sh);
    for (int i = tid; i < 5184; i += 128) ws[i] = w[i];
    __syncthreads();

    for (int e = tid; e < 24*154; e += 128) {
        int ci = e / 154, r2 = e - ci*154;
        int ly = r2 / 14, lx = r2 - ly*14;
        int iy = ly - 1, ix = lx - 1;
        float v = 0.f;
        if (lx < 11 && iy >= 0 && iy < 10 && ix >= 0 && ix < 10)
            v = fmaf(in[((size_t)n*24 + ci)*100 + iy*10 + ix], sc[ci], sh[ci]);
        tile[e] = v;
    }
    __syncthreads();

    if (tid < 120) {
        const int co = tid / 5;
        const int r  = tid % 5;

        float acc[5];
        const float bq = cb[co];
        #pragma unroll
        for (int c = 0; c < 5; c++) acc[c] = bq;
        #pragma unroll 4
        for (int ci = 0; ci < 24; ci++) {
            const float* tb = tile + ci*154;
            #pragma unroll
            for (int ky = 0; ky < 3; ky++) {
                const float2* row = (const float2*)(tb + (2*r + ky)*14);
                float x[12];
                #pragma unroll
                for (int t = 0; t < 6; t++) {
                    float2 v = row[t];
                    x[2*t] = v.x; x[2*t+1] = v.y;
                }
                const float* wr = ws + co*216 + ci*9 + ky*3;
                const float w0 = wr[0], w1 = wr[1], w2 = wr[2];
                #pragma unroll
                for (int c = 0; c < 5; c++)
                    acc[c] = fmaf(x[2*c], w0, fmaf(x[2*c+1], w1,
                               fmaf(x[2*c+2], w2, acc[c])));
            }
        }
        float s1 = 0.f, s2 = 0.f;
        float* op = out + ((size_t)n*24 + co)*25 + r*5;
        #pragma unroll
        for (int c = 0; c < 5; c++) {
            float y = fmaxf(acc[c], 0.f);
            op[c] = y;
            s1 += y; s2 += y*y;
        }
        rd1[co*5 + r] = s1;
        rd2[co*5 + r] = s2;
    }
    __syncthreads();
    if (tid < 48) {
        const int co2 = tid % 24, st = tid / 24;
        const float* rd = (st ? rd2 : rd1) + co2*5;
        float s = 0.f;
        #pragma unroll
        for (int i = 0; i < 5; i++) s += rd[i];
        atomicAdd(&d_stats[3*48 + st*24 + co2], s);
    }
}

// -------------------- proj: per-batch, register weights ----------------------
__global__ void __launch_bounds__(256)
proj_kernel(const float* __restrict__ qst, const float* __restrict__ g1b,
            const float* __restrict__ bg4, const float* __restrict__ bb4) {
    __shared__ float sc[24], sh[24];
    __shared__ float feat[NOBJ][26];
    __shared__ float qv[11];
    const int b   = blockIdx.x;
    const int tid = threadIdx.x;

    bn_derive(tid, 3, 1.f/(NB*25.f), bg4, bb4, sc, sh);
    if (tid >= 32 && tid < 43) qv[tid - 32] = qst[(tid - 32)*NB + b];
    __syncthreads();

    for (int e = tid; e < NOBJ*24; e += 256) {
        int o = e / 24, c = e - o*24;
        feat[o][c] = fmaf(d_y4[((size_t)b*24 + c)*25 + o], sc[c], sh[c]);
    }
    if (tid < 2*NOBJ) {
        int o = tid >> 1;
        if (tid & 1) feat[o][25] = ((float)(o % 5) - 2.f) * 0.5f;
        else         feat[o][24] = ((float)(o / 5) - 2.f) * 0.5f;
    }

    const int n = tid;
    float wp[26], wq[26];
    #pragma unroll
    for (int c = 0; c < 26; c++) {
        wp[c] = d_g1t[c*HID + n];
        wq[c] = d_g1t[(26 + c)*HID + n];
    }
    float rr = g1b[n];
    #pragma unroll
    for (int c = 0; c < 11; c++) rr = fmaf(d_g1t[(52 + c)*HID + n], qv[c], rr);
    __syncthreads();
    d_R[(size_t)b*HID + n] = __float2half(rr);

    #pragma unroll 1
    for (int o = 0; o < NOBJ; o++) {
        float p = 0.f, q = 0.f;
        #pragma unroll
        for (int c = 0; c < 26; c++) {
            const float f = feat[o][c];
            p = fmaf(wp[c], f, p);
            q = fmaf(wq[c], f, q);
        }
        d_P[((size_t)b*NOBJ + o)*HID + n] = __float2half(p);
        d_Q[((size_t)b*NOBJ + o)*HID + n] = __float2half(q);
    }
}

// ------------------ fp16 mma g2/g3/g4 fused MLP (verified) -------------------
__device__ __forceinline__ void load_W_async(uint32_t sb, const __half* W, int tid) {
    #pragma unroll 8
    for (int it = 0; it < 32; it++) {
        int idx = it*256 + tid;
        int n = idx >> 5;
        int c = idx & 31;
        uint32_t dst = sb + SM_W + n*LDAB + c*16;
        size_t src = __cvta_generic_to_global((const char*)(W + n*HID) + c*16);
        asm volatile("cp.async.cg.shared.global [%0], [%1], 16;\n" :: "r"(dst), "l"(src));
    }
    asm volatile("cp.async.commit_group;\n" ::: "memory");
}

__global__ void __launch_bounds__(256, 1)
gmlp_mma_kernel(const float* __restrict__ g2b, const float* __restrict__ g3b,
                const float* __restrict__ g4b) {
    extern __shared__ char smem[];
    const uint32_t sb = smem_u32(smem);
    float* bias_s = (float*)smem;

    const int tid  = threadIdx.x;
    const int wid  = tid >> 5;
    const int lane = tid & 31;
    const int blk  = blockIdx.x;
    const int b    = blk / GTILES;
    const int t    = blk - b*GTILES;
    const int row0 = t * 128;
    const int valid = (NPAIR - row0 < 128) ? (NPAIR - row0) : 128;

    load_W_async(sb, d_Wh, tid);

    bias_s[tid]       = g2b[tid];
    bias_s[256 + tid] = g3b[tid];
    bias_s[512 + tid] = g4b[tid];
    if (tid < 128) {
        bias_s[128 + tid]       = g2b[128 + tid];
        bias_s[256 + 128 + tid] = g3b[128 + tid];
        bias_s[512 + 128 + tid] = g4b[128 + tid];
    }

    const __half* Ph = d_P + (size_t)b*NOBJ*HID;
    const __half* Qh = d_Q + (size_t)b*NOBJ*HID;
    const __half* Rh = d_R + (size_t)b*HID;
    #pragma unroll 4
    for (int it = 0; it < 16; it++) {
        int v = it*256 + tid;
        int m = v >> 5;
        int u = v & 31;
        int k0 = u * 8;
        uint4 o = {0u, 0u, 0u, 0u};
        if (m < valid) {
            int p = row0 + m;
            int j = p / NOBJ;
            int i = p - j*NOBJ;
            uint4 P4 = *(const uint4*)(Ph + i*HID + k0);
            uint4 Q4 = *(const uint4*)(Qh + j*HID + k0);
            uint4 R4 = *(const uint4*)(Rh + k0);
            o.x = h2relu3(P4.x, Q4.x, R4.x);
            o.y = h2relu3(P4.y, Q4.y, R4.y);
            o.z = h2relu3(P4.z, Q4.z, R4.z);
            o.w = h2relu3(P4.w, Q4.w, R4.w);
        }
        uint32_t addr = sb + SM_H + m*LDAB + u*16;
        asm volatile("st.shared.v4.b32 [%0], {%1,%2,%3,%4};" :: "r"(addr),
                     "r"(o.x), "r"(o.y), "r"(o.z), "r"(o.w));
    }
    asm volatile("cp.async.wait_group 0;\n" ::: "memory");
    __syncthreads();

    const int m0 = (wid & 1) * 64;
    const int n0 = (wid >> 1) * 64;
    const uint32_t aAddr0 = sb + SM_H + (m0 + (lane & 15))*LDAB + (8*(lane >> 4))*2;
    const uint32_t bAddr0 = sb + SM_W + (n0 + (lane & 7) + (lane >> 4)*8)*LDAB
                                       + (((lane >> 3) & 1)*8)*2;

    for (int L = 0; L < 3; L++) {
        float acc[4][8][4];
        #pragma unroll
        for (int mi = 0; mi < 4; mi++)
            #pragma unroll
            for (int nj = 0; nj < 8; nj++)
                #pragma unroll
                for (int e = 0; e < 4; e++) acc[mi][nj][e] = 0.f;

        #pragma unroll 1
        for (int ks = 0; ks < 16; ks++) {
            const uint32_t koff = ks * 32;
            uint32_t a[4][4], bfr[4][4];
            #pragma unroll
            for (int mi = 0; mi < 4; mi++)
                ldsm_x4(a[mi], aAddr0 + mi*16*LDAB + koff);
            #pragma unroll
            for (int nt = 0; nt < 4; nt++)
                ldsm_x4(bfr[nt], bAddr0 + nt*16*LDAB + koff);
            #pragma unroll
            for (int mi = 0; mi < 4; mi++)
                #pragma unroll
                for (int nt = 0; nt < 4; nt++) {
                    mma16816(acc[mi][nt*2],     a[mi], bfr[nt][0], bfr[nt][1]);
                    mma16816(acc[mi][nt*2 + 1], a[mi], bfr[nt][2], bfr[nt][3]);
                }
        }
        __syncthreads();

        if (L < 2) {
            load_W_async(sb, d_Wh + (size_t)(L+1)*HID*HID, tid);
            const float* bl = bias_s + L*256;
            #pragma unroll
            for (int mi = 0; mi < 4; mi++) {
                const int r0 = m0 + mi*16 + lane/4;
                #pragma unroll
                for (int nj = 0; nj < 8; nj++) {
                    const int c0 = n0 + nj*8 + (lane & 3)*2;
                    __half2 q0 = __floats2half2_rn(
                        fmaxf(acc[mi][nj][0] + bl[c0],     0.f),
                        fmaxf(acc[mi][nj][1] + bl[c0 + 1], 0.f));
                    __half2 q1 = __floats2half2_rn(
                        fmaxf(acc[mi][nj][2] + bl[c0],     0.f),
                        fmaxf(acc[mi][nj][3] + bl[c0 + 1], 0.f));
                    *(uint32_t*)(smem + SM_H + r0*LDAB + c0*2)       = *(uint32_t*)&q0;
                    *(uint32_t*)(smem + SM_H + (r0 + 8)*LDAB + c0*2) = *(uint32_t*)&q1;
                }
            }
            asm volatile("cp.async.wait_group 0;\n" ::: "memory");
            __syncthreads();
        } else {
            const float* bl = bias_s + 512;
            #pragma unroll
            for (int nj = 0; nj < 8; nj++) {
                const int c0 = n0 + nj*8 + (lane & 3)*2;
                float v0 = 0.f, v1 = 0.f;
                #pragma unroll
                for (int mi = 0; mi < 4; mi++) {
                    const int ra = m0 + mi*16 + lane/4;
                    if (ra < valid) {
                        v0 += fmaxf(acc[mi][nj][0] + bl[c0],     0.f);
                        v1 += fmaxf(acc[mi][nj][1] + bl[c0 + 1], 0.f);
                    }
                    if (ra + 8 < valid) {
                        v0 += fmaxf(acc[mi][nj][2] + bl[c0],     0.f);
                        v1 += fmaxf(acc[mi][nj][3] + bl[c0 + 1], 0.f);
                    }
                }
                #pragma unroll
                for (int off = 4; off < 32; off <<= 1) {
                    v0 += __shfl_xor_sync(0xffffffffu, v0, off);
                    v1 += __shfl_xor_sync(0xffffffffu, v1, off);
                }
                if (lane < 4) {
                    atomicAdd(&d_xg[(size_t)b*HID + c0],     v0);
                    atomicAdd(&d_xg[(size_t)b*HID + c0 + 1], v1);
                }
            }
        }
    }
}

// ------------------------------- head (8 batches/block) ----------------------
__global__ void __launch_bounds__(256)
head_kernel(const float* __restrict__ f1b, const float* __restrict__ fc2b,
            const float* __restrict__ fc3w, const float* __restrict__ fc3b,
            float* __restrict__ out) {
    __shared__ float xa[8][HID], xb[8][HID];
    __shared__ float lg[8][10];
    const int b0 = blockIdx.x * 8;
    const int n  = threadIdx.x;
    const float* f1wt  = d_Wt;
    const float* fc2wt = d_Wt + HID*HID;

    #pragma unroll
    for (int bi = 0; bi < 8; bi++) xa[bi][n] = d_xg[(size_t)(b0 + bi)*HID + n];
    __syncthreads();

    {
        float a[8];
        const float bb = f1b[n];
        #pragma unroll
        for (int bi = 0; bi < 8; bi++) a[bi] = bb;
        for (int k = 0; k < HID; k++) {
            const float w = f1wt[k*HID + n];
            #pragma unroll
            for (int bi = 0; bi < 8; bi++) a[bi] = fmaf(w, xa[bi][k], a[bi]);
        }
        #pragma unroll
        for (int bi = 0; bi < 8; bi++) xb[bi][n] = fmaxf(a[bi], 0.f);
    }
    __syncthreads();
    {
        float a[8];
        const float bb = fc2b[n];
        #pragma unroll
        for (int bi = 0; bi < 8; bi++) a[bi] = bb;
        for (int k = 0; k < HID; k++) {
            const float w = fc2wt[k*HID + n];
            #pragma unroll
            for (int bi = 0; bi < 8; bi++) a[bi] = fmaf(w, xb[bi][k], a[bi]);
        }
        #pragma unroll
        for (int bi = 0; bi < 8; bi++) xa[bi][n] = fmaxf(a[bi], 0.f);
    }
    __syncthreads();

    if (n < 80) {
        const int co = n % 10, bi = n / 10;
        float l = fc3b[co];
        const float* wr = fc3w + co*HID;
        for (int k = 0; k < HID; k++) l = fmaf(wr[k], xa[bi][k], l);
        lg[bi][co] = l;
    }
    __syncthreads();
    if (n < 8) {
        float mx = lg[n][0];
        #pragma unroll
        for (int c = 1; c < 10; c++) mx = fmaxf(mx, lg[n][c]);
        float se = 0.f;
        #pragma unroll
        for (int c = 0; c < 10; c++) se += expf(lg[n][c] - mx);
        const float lse = mx + logf(se);
        #pragma unroll
        for (int c = 0; c < 10; c++) out[(b0 + n)*10 + c] = lg[n][c] - lse;
    }
}

// ----------------------------- launcher --------------------------------------
extern "C" void kernel_launch(void* const* d_in, const int* in_sizes, int n_in,
                              void* d_out, int out_size) {
    const float* img  = (const float*)d_in[0];
    const float* qst  = (const float*)d_in[1];
    const float* cw1  = (const float*)d_in[2];
    const float* cb1  = (const float*)d_in[3];
    const float* bg1  = (const float*)d_in[4];
    const float* bb1  = (const float*)d_in[5];
    const float* cw2  = (const float*)d_in[6];
    const float* cb2  = (const float*)d_in[7];
    const float* bg2  = (const float*)d_in[8];
    const float* bb2  = (const float*)d_in[9];
    const float* cw3  = (const float*)d_in[10];
    const float* cb3  = (const float*)d_in[11];
    const float* bg3  = (const float*)d_in[12];
    const float* bb3  = (const float*)d_in[13];
    const float* cw4  = (const float*)d_in[14];
    const float* cb4  = (const float*)d_in[15];
    const float* bg4  = (const float*)d_in[16];
    const float* bb4  = (const float*)d_in[17];
    const float* g1w  = (const float*)d_in[18];
    const float* g1b  = (const float*)d_in[19];
    const float* g2w  = (const float*)d_in[20];
    const float* g2b  = (const float*)d_in[21];
    const float* g3w  = (const float*)d_in[22];
    const float* g3b  = (const float*)d_in[23];
    const float* g4w  = (const float*)d_in[24];
    const float* g4b  = (const float*)d_in[25];
    const float* f1w  = (const float*)d_in[26];
    const float* f1b  = (const float*)d_in[27];
    const float* fc2w = (const float*)d_in[28];
    const float* fc2b = (const float*)d_in[29];
    const float* fc3w = (const float*)d_in[30];
    const float* fc3b = (const float*)d_in[31];
    float* out = (float*)d_out;

    float *y1, *y2, *y3, *y4;
    cudaGetSymbolAddress((void**)&y1, d_y1);
    cudaGetSymbolAddress((void**)&y2, d_y2);
    cudaGetSymbolAddress((void**)&y3, d_y3);
    cudaGetSymbolAddress((void**)&y4, d_y4);

    cudaFuncSetAttribute(gmlp_mma_kernel, cudaFuncAttributeMaxDynamicSharedMemorySize, SM_TOTAL);
    cudaFuncSetAttribute(conv2_kernel, cudaFuncAttributeMaxDynamicSharedMemorySize, C2_BYTES);
    cudaFuncSetAttribute(conv3_kernel, cudaFuncAttributeMaxDynamicSharedMemorySize, C2_BYTES);
    cudaFuncSetAttribute(conv4_kernel, cudaFuncAttributeMaxDynamicSharedMemorySize, C4_BYTES);

    prep_kernel<<<768, 256>>>(g2w, g3w, g4w, f1w, fc2w, g1w);

    conv1_kernel<<<dim3(16, NB), 256>>>(img, y1, cw1, cb1);
    conv2_kernel<<<dim3(4, NB), 128, C2_BYTES>>>(y1, y2, cw2, cb2, bg1, bb1);
    conv3_kernel<<<dim3(1, NB), 128, C2_BYTES>>>(y2, y3, cw3, cb3, bg2, bb2);
    conv4_kernel<<<dim3(1, NB), 128, C4_BYTES>>>(y3, y4, cw4, cb4, bg3, bb3);

    proj_kernel<<<NB, 256>>>(qst, g1b, bg4, bb4);

    gmlp_mma_kernel<<<NB*GTILES, 256, SM_TOTAL>>>(g2b, g3b, g4b);

    head_kernel<<<NB/8, 256>>>(f1b, fc2b, fc3w, fc3b, out);
}